// round 1
// baseline (speedup 1.0000x reference)
#include <cuda_runtime.h>
#include <cstddef>

// ---------------- device scratch (no allocations allowed) ----------------
__device__ float g_x1[8192 * 256];
__device__ float g_x2[8192 * 128];
__device__ float g_x3[8192 * 64];
__device__ float g_t [8192 * 256];   // reused for T1/T2/T3 (max Y = 256)
__device__ float g_invnx[8192];
__device__ float g_sb[8192];
__device__ float g_cb[8192];
__device__ float g_part[64 * 256];   // partial hebb sums (64 row-chunks)
__device__ float g_rsH[256];

// ---------------- reduction helper ----------------
__device__ __forceinline__ float warp_sum(float v) {
#pragma unroll
    for (int o = 16; o; o >>= 1) v += __shfl_down_sync(0xffffffffu, v, o);
    return v;
}

// ---------------- per-row norm + sum of activation ----------------
__global__ void rowstats_kernel(const float* __restrict__ X, int D,
                                float* __restrict__ invn, float* __restrict__ rs) {
    int b = blockIdx.x;
    const float* row = X + (size_t)b * D;
    float s = 0.f, ss = 0.f;
    for (int i = threadIdx.x; i < D; i += blockDim.x) {
        float v = row[i];
        s += v;
        ss = fmaf(v, v, ss);
    }
    __shared__ float shs[8], shss[8];
    s = warp_sum(s);
    ss = warp_sum(ss);
    int w = threadIdx.x >> 5, l = threadIdx.x & 31;
    if (l == 0) { shs[w] = s; shss[w] = ss; }
    __syncthreads();
    if (threadIdx.x == 0) {
        float ts = 0.f, tss = 0.f;
#pragma unroll
        for (int i = 0; i < 8; i++) { ts += shs[i]; tss += shss[i]; }
        invn[b] = rsqrtf(tss);
        rs[b] = ts;
    }
}

// ---------------- fused GEMM: out[m,n] = sum_k A[m,k]*Wcat[n,k] ----------------
// Columns [0,NW) -> relu(+bias)*mask -> Xout ; columns [NW,NW+NT) -> raw -> Tout
template <int BM, int BN, int BK>
__global__ __launch_bounds__(256)
void gemm_fused(const float* __restrict__ A,
                const float* __restrict__ W,
                const float* __restrict__ Hm,
                const float* __restrict__ bias,
                const float* __restrict__ mask,
                float* __restrict__ Xout,
                float* __restrict__ Tout,
                int M, int K, int NW, int NT) {
    constexpr int TM = BM / 16;
    constexpr int TN = BN / 16;
    const int N = NW + NT;
    __shared__ float As[BK][BM + 4];
    __shared__ float Bs[BK][BN + 4];
    const int bm = blockIdx.y * BM;
    const int bn = blockIdx.x * BN;
    const int tid = threadIdx.x;
    const int tx = tid & 15, ty = tid >> 4;

    float acc[TM][TN];
#pragma unroll
    for (int i = 0; i < TM; i++)
#pragma unroll
        for (int j = 0; j < TN; j++) acc[i][j] = 0.f;

    for (int k0 = 0; k0 < K; k0 += BK) {
#pragma unroll
        for (int i = 0; i < (BM * BK) / 256; i++) {
            int lin = tid + i * 256;
            int r = lin / BK, c = lin % BK;
            As[c][r] = A[(size_t)(bm + r) * K + k0 + c];
        }
#pragma unroll
        for (int i = 0; i < (BN * BK) / 256; i++) {
            int lin = tid + i * 256;
            int r = lin / BK, c = lin % BK;
            int n = bn + r;
            float v = 0.f;
            if (n < NW)      v = W[(size_t)n * K + k0 + c];
            else if (n < N)  v = Hm[(size_t)(n - NW) * K + k0 + c];
            Bs[c][r] = v;
        }
        __syncthreads();
#pragma unroll
        for (int kk = 0; kk < BK; kk++) {
            float a[TM], b[TN];
#pragma unroll
            for (int i = 0; i < TM; i += 4)
                *(float4*)&a[i] = *(const float4*)&As[kk][ty * TM + i];
#pragma unroll
            for (int j = 0; j < TN; j += 4)
                *(float4*)&b[j] = *(const float4*)&Bs[kk][tx * TN + j];
#pragma unroll
            for (int i = 0; i < TM; i++)
#pragma unroll
                for (int j = 0; j < TN; j++)
                    acc[i][j] = fmaf(a[i], b[j], acc[i][j]);
        }
        __syncthreads();
    }

#pragma unroll
    for (int i = 0; i < TM; i++) {
        int m = bm + ty * TM + i;
#pragma unroll
        for (int j = 0; j < TN; j++) {
            int n = bn + tx * TN + j;
            if (n < NW) {
                float v = acc[i][j] + bias[n];
                v = fmaxf(v, 0.f);
                if (mask) v *= mask[n];
                Xout[(size_t)m * NW + n] = v;
            } else if (n < N) {
                Tout[(size_t)m * NT + (n - NW)] = acc[i][j];
            }
        }
    }
}

// ---------------- c_b = s_b / (||x_b|| * ||t_b||) (one warp per row of T) ----------------
__global__ void cb_kernel(const float* __restrict__ T, int Y,
                          const float* __restrict__ invnx, const float* __restrict__ sb,
                          float* __restrict__ cb) {
    int warp = (blockIdx.x * blockDim.x + threadIdx.x) >> 5;
    int lane = threadIdx.x & 31;
    if (warp >= 8192) return;
    const float* row = T + (size_t)warp * Y;
    float ss = 0.f;
    for (int i = lane; i < Y; i += 32) { float v = row[i]; ss = fmaf(v, v, ss); }
    ss = warp_sum(ss);
    if (lane == 0) cb[warp] = sb[warp] * invnx[warp] * rsqrtf(ss);
}

// ---------------- hebb partials: part[blk, j] = sum_{b in chunk} T[b,j]*c_b ----------------
__global__ void hebb_kernel(const float* __restrict__ T, int Y,
                            const float* __restrict__ cb, float* __restrict__ part,
                            int rows_per_blk) {
    int j = threadIdx.x;              // blockDim == Y
    int b0 = blockIdx.x * rows_per_blk;
    float acc = 0.f;
    for (int b = b0; b < b0 + rows_per_blk; b++)
        acc = fmaf(T[(size_t)b * Y + j], cb[b], acc);
    part[blockIdx.x * Y + j] = acc;
}

// ---------------- rowsum of H (one warp per row) ----------------
__global__ void rowsum_kernel(const float* __restrict__ H, int Y, int D,
                              float* __restrict__ out) {
    int row = (blockIdx.x * blockDim.x + threadIdx.x) >> 5;
    int lane = threadIdx.x & 31;
    if (row >= Y) return;
    float s = 0.f;
    for (int i = lane; i < D; i += 32) s += H[(size_t)row * D + i];
    s = warp_sum(s);
    if (lane == 0) out[row] = s;
}

// ---------------- final score -> mask (single block, blockDim == Y) ----------------
__global__ void score_kernel(const float* __restrict__ rsH, const float* __restrict__ part,
                             int Y, float* __restrict__ hm) {
    int j = threadIdx.x;
    float hb = 0.f;
    for (int p = 0; p < 64; p++) hb += part[p * Y + j];
    float theta = 1.0f / (float)Y;
    float sc = fmaf(1.0f - theta, rsH[j], hb);
    __shared__ float smin[256], smax[256];
    smin[j] = sc; smax[j] = sc;
    __syncthreads();
    for (int s = blockDim.x >> 1; s > 0; s >>= 1) {
        if (j < s) {
            smin[j] = fminf(smin[j], smin[j + s]);
            smax[j] = fmaxf(smax[j], smax[j + s]);
        }
        __syncthreads();
    }
    float mn = smin[0], mx = smax[0];
    float norm = (sc - mn) / (mx - mn + 1e-8f);
    hm[j] = (norm < 0.5f) ? 0.0f : 1.0f;
}

// ---------------- launcher ----------------
extern "C" void kernel_launch(void* const* d_in, const int* in_sizes, int n_in,
                              void* d_out, int out_size) {
    const float* x     = (const float*)d_in[0];
    const float* mask0 = (const float*)d_in[1];
    const float* mask1 = (const float*)d_in[2];
    const float* mask2 = (const float*)d_in[3];
    const float* W1 = (const float*)d_in[4];
    const float* b1 = (const float*)d_in[5];
    const float* W2 = (const float*)d_in[6];
    const float* b2 = (const float*)d_in[7];
    const float* W3 = (const float*)d_in[8];
    const float* b3 = (const float*)d_in[9];
    const float* W4 = (const float*)d_in[10];
    const float* b4 = (const float*)d_in[11];
    const float* H1 = (const float*)d_in[12];
    const float* H2 = (const float*)d_in[13];
    const float* H3 = (const float*)d_in[14];
    float* out = (float*)d_out;

    float *x1, *x2, *x3, *t, *invnx, *sb, *cb, *part, *rsH;
    cudaGetSymbolAddress((void**)&x1, g_x1);
    cudaGetSymbolAddress((void**)&x2, g_x2);
    cudaGetSymbolAddress((void**)&x3, g_x3);
    cudaGetSymbolAddress((void**)&t,  g_t);
    cudaGetSymbolAddress((void**)&invnx, g_invnx);
    cudaGetSymbolAddress((void**)&sb, g_sb);
    cudaGetSymbolAddress((void**)&cb, g_cb);
    cudaGetSymbolAddress((void**)&part, g_part);
    cudaGetSymbolAddress((void**)&rsH, g_rsH);

    const int B = 8192;
    const size_t OUT_OFF = (size_t)B * 1000;

    // ---- layer 1: x (K=1024) -> x1 (256) + T1 (256) ----
    rowstats_kernel<<<B, 256>>>(x, 1024, invnx, sb);
    gemm_fused<128, 128, 16><<<dim3(4, B / 128), 256>>>(
        x, W1, H1, b1, mask0, x1, t, B, 1024, 256, 256);
    cb_kernel<<<B / 8, 256>>>(t, 256, invnx, sb, cb);
    hebb_kernel<<<64, 256>>>(t, 256, cb, part, B / 64);
    rowsum_kernel<<<32, 256>>>(H1, 256, 1024, rsH);
    score_kernel<<<1, 256>>>(rsH, part, 256, out + OUT_OFF);

    // ---- layer 2: x1 (K=256) -> x2 (128) + T2 (128) ----
    rowstats_kernel<<<B, 256>>>(x1, 256, invnx, sb);
    gemm_fused<64, 64, 16><<<dim3(4, B / 64), 256>>>(
        x1, W2, H2, b2, mask1, x2, t, B, 256, 128, 128);
    cb_kernel<<<B / 8, 256>>>(t, 128, invnx, sb, cb);
    hebb_kernel<<<64, 128>>>(t, 128, cb, part, B / 64);
    rowsum_kernel<<<16, 256>>>(H2, 128, 256, rsH);
    score_kernel<<<1, 128>>>(rsH, part, 128, out + OUT_OFF + 256);

    // ---- layer 3: x2 (K=128) -> x3 (64) + T3 (64) ----
    rowstats_kernel<<<B, 256>>>(x2, 128, invnx, sb);
    gemm_fused<64, 64, 16><<<dim3(2, B / 64), 256>>>(
        x2, W3, H3, b3, mask2, x3, t, B, 128, 64, 64);
    cb_kernel<<<B / 8, 256>>>(t, 64, invnx, sb, cb);
    hebb_kernel<<<64, 64>>>(t, 64, cb, part, B / 64);
    rowsum_kernel<<<8, 256>>>(H3, 64, 128, rsH);
    score_kernel<<<1, 64>>>(rsH, part, 64, out + OUT_OFF + 384);

    // ---- layer 4: x3 (K=64) -> out (1000), relu, no mask, no hebbian ----
    gemm_fused<128, 128, 16><<<dim3(8, B / 128), 256>>>(
        x3, W4, (const float*)nullptr, b4, (const float*)nullptr,
        out, (float*)nullptr, B, 64, 1000, 0);
}

// round 3
// speedup vs baseline: 2.9264x; 2.9264x over previous
#include <cuda_runtime.h>
#include <cuda_bf16.h>
#include <cstdint>
#include <cstddef>

// ================= device scratch (no allocations allowed) =================
__device__ float g_x1[8192 * 256];
__device__ float g_x2[8192 * 128];
__device__ float g_x3[8192 * 64];
__device__ float g_t [8192 * 256];   // reused for T1/T2/T3 (max Y = 256)
__device__ float g_invnx[8192];
__device__ float g_sb[8192];
__device__ float g_cb[8192];
__device__ float g_part[256 * 256];  // partial hebb sums (256 row-chunks)
__device__ float g_rsH[256];

// ================= warp-mma helpers (generic ISA, works on plain sm_103) ====
__device__ __forceinline__ uint32_t smem_u32(const void* p) {
    uint32_t a;
    asm("{ .reg .u64 t; cvta.to.shared.u64 t, %1; cvt.u32.u64 %0, t; }"
        : "=r"(a) : "l"(p));
    return a;
}

__device__ __forceinline__ void ldsm4(uint32_t* r, uint32_t addr) {
    asm volatile("ldmatrix.sync.aligned.m8n8.x4.shared.b16 {%0,%1,%2,%3}, [%4];"
                 : "=r"(r[0]), "=r"(r[1]), "=r"(r[2]), "=r"(r[3]) : "r"(addr));
}

__device__ __forceinline__ void mma16816(float* d, const uint32_t* a, const uint32_t* b) {
    asm volatile(
        "mma.sync.aligned.m16n8k16.row.col.f32.bf16.bf16.f32 "
        "{%0,%1,%2,%3}, {%4,%5,%6,%7}, {%8,%9}, {%0,%1,%2,%3};"
        : "+f"(d[0]), "+f"(d[1]), "+f"(d[2]), "+f"(d[3])
        : "r"(a[0]), "r"(a[1]), "r"(a[2]), "r"(a[3]), "r"(b[0]), "r"(b[1]));
}

__device__ __forceinline__ uint32_t pack_bf16(float a, float b) {
    __nv_bfloat162 t = __floats2bfloat162_rn(a, b);
    return *reinterpret_cast<uint32_t*>(&t);
}

// split float4 -> hi pair / lo pair (packed bf16x2)
__device__ __forceinline__ void split_hilo(float4 v, uint32_t& h01, uint32_t& h23,
                                           uint32_t& l01, uint32_t& l23) {
    float hx = __bfloat162float(__float2bfloat16(v.x));
    float hy = __bfloat162float(__float2bfloat16(v.y));
    float hz = __bfloat162float(__float2bfloat16(v.z));
    float hw = __bfloat162float(__float2bfloat16(v.w));
    h01 = pack_bf16(hx, hy);
    h23 = pack_bf16(hz, hw);
    l01 = pack_bf16(v.x - hx, v.y - hy);
    l23 = pack_bf16(v.z - hz, v.w - hw);
}

// ================= bf16 3-pass tensor-core fused GEMM =================
// D[m,n] = sum_k A[m,k] * Bcat[n,k], Bcat = [W(NW rows); Hm(NT rows)]
// Epilogue: n<NW -> relu(v+bias)*mask -> Xout ; NW<=n<NW+NT -> raw -> Tout
// CTA tile 128x128, 8 warps (warp tile 32x64), K-chunk 32, double buffered.
#define KC      32
#define LDH     40                      // halfword stride (32 + 8 pad)
#define A_HI    0
#define A_LO    (128 * LDH * 2)         // 10240 B
#define B_HI    (2 * 128 * LDH * 2)
#define B_LO    (3 * 128 * LDH * 2)
#define STAGE_B (4 * 128 * LDH * 2)     // 40960 B
#define GEMM_SMEM (2 * STAGE_B)         // 81920 B

__global__ __launch_bounds__(256)
void gemm_mma(const float* __restrict__ A, const float* __restrict__ W,
              const float* __restrict__ Hm, const float* __restrict__ bias,
              const float* __restrict__ mask,
              float* __restrict__ Xout, float* __restrict__ Tout,
              int K, int NW, int NT) {
    extern __shared__ char smem[];
    const uint32_t sbase = smem_u32(smem);
    const int tid  = threadIdx.x;
    const int lane = tid & 31;
    const int warp = tid >> 5;
    const int wm = warp >> 1;           // 0..3  (m offset 32 each)
    const int wn = warp & 1;            // 0..1  (n offset 64 each)
    const int bm = blockIdx.y * 128;
    const int bn = blockIdx.x * 128;
    const int Ntot = NW + NT;

    // loader mapping: each thread loads 4 rows (row0 + 32*i), 4 floats (quad*4)
    const int lrow = tid >> 3;          // 0..31
    const int quad = tid & 7;           // 0..7

    float acc[2][8][4];
#pragma unroll
    for (int i = 0; i < 2; i++)
#pragma unroll
        for (int j = 0; j < 8; j++)
#pragma unroll
            for (int q = 0; q < 4; q++) acc[i][j][q] = 0.f;

    const int NC = K / KC;

    // ---- prologue: load + convert chunk 0 into stage 0 ----
    {
        char* st = smem;
#pragma unroll
        for (int i = 0; i < 4; i++) {
            int r = lrow + 32 * i;
            float4 va = *reinterpret_cast<const float4*>(
                A + (size_t)(bm + r) * K + quad * 4);
            int nn = bn + r;
            float4 vb = make_float4(0.f, 0.f, 0.f, 0.f);
            if (nn < NW)
                vb = *reinterpret_cast<const float4*>(W + (size_t)nn * K + quad * 4);
            else if (nn < Ntot)
                vb = *reinterpret_cast<const float4*>(Hm + (size_t)(nn - NW) * K + quad * 4);
            uint32_t h01, h23, l01, l23;
            uint32_t off = (uint32_t)(r * LDH + quad * 4) * 2;
            split_hilo(va, h01, h23, l01, l23);
            *reinterpret_cast<uint2*>(st + A_HI + off) = make_uint2(h01, h23);
            *reinterpret_cast<uint2*>(st + A_LO + off) = make_uint2(l01, l23);
            split_hilo(vb, h01, h23, l01, l23);
            *reinterpret_cast<uint2*>(st + B_HI + off) = make_uint2(h01, h23);
            *reinterpret_cast<uint2*>(st + B_LO + off) = make_uint2(l01, l23);
        }
    }
    __syncthreads();

    for (int c = 0; c < NC; c++) {
        // ---- issue global loads for chunk c+1 ----
        float4 avn[4], bvn[4];
        if (c + 1 < NC) {
            const int k0 = (c + 1) * KC;
#pragma unroll
            for (int i = 0; i < 4; i++) {
                int r = lrow + 32 * i;
                avn[i] = *reinterpret_cast<const float4*>(
                    A + (size_t)(bm + r) * K + k0 + quad * 4);
                int nn = bn + r;
                bvn[i] = make_float4(0.f, 0.f, 0.f, 0.f);
                if (nn < NW)
                    bvn[i] = *reinterpret_cast<const float4*>(
                        W + (size_t)nn * K + k0 + quad * 4);
                else if (nn < Ntot)
                    bvn[i] = *reinterpret_cast<const float4*>(
                        Hm + (size_t)(nn - NW) * K + k0 + quad * 4);
            }
        }

        // ---- compute chunk c from stage (c&1) ----
        {
            const uint32_t stb = sbase + (uint32_t)(c & 1) * STAGE_B;
#pragma unroll
            for (int kk = 0; kk < KC; kk += 16) {
                // A frags: 2 m-tiles, hi + lo
                uint32_t ah[2][4], al[2][4];
                {
                    int rl = lane & 15;
                    int ka = (lane >> 4) * 8;
#pragma unroll
                    for (int i = 0; i < 2; i++) {
                        uint32_t off =
                            (uint32_t)((wm * 32 + i * 16 + rl) * LDH + kk + ka) * 2;
                        ldsm4(ah[i], stb + A_HI + off);
                        ldsm4(al[i], stb + A_LO + off);
                    }
                }
                // B frags: 8 n-tiles via 4 ldsm4 pairs, hi + lo
                uint32_t bh[8][2], bl[8][2];
                {
                    int rl = lane & 7;
                    int sec = lane >> 3;
                    int nloc = ((sec & 2) ? 8 : 0) + rl;
                    int ka = (sec & 1) * 8;
#pragma unroll
                    for (int p = 0; p < 4; p++) {
                        uint32_t off =
                            (uint32_t)((wn * 64 + p * 16 + nloc) * LDH + kk + ka) * 2;
                        uint32_t r4[4];
                        ldsm4(r4, stb + B_HI + off);
                        bh[2 * p][0] = r4[0]; bh[2 * p][1] = r4[1];
                        bh[2 * p + 1][0] = r4[2]; bh[2 * p + 1][1] = r4[3];
                        ldsm4(r4, stb + B_LO + off);
                        bl[2 * p][0] = r4[0]; bl[2 * p][1] = r4[1];
                        bl[2 * p + 1][0] = r4[2]; bl[2 * p + 1][1] = r4[3];
                    }
                }
#pragma unroll
                for (int i = 0; i < 2; i++)
#pragma unroll
                    for (int j = 0; j < 8; j++) {
                        mma16816(acc[i][j], ah[i], bh[j]);
                        mma16816(acc[i][j], ah[i], bl[j]);
                        mma16816(acc[i][j], al[i], bh[j]);
                    }
            }
        }

        // ---- convert + store chunk c+1 into stage ((c+1)&1) ----
        if (c + 1 < NC) {
            char* st = smem + ((c + 1) & 1) * STAGE_B;
#pragma unroll
            for (int i = 0; i < 4; i++) {
                int r = lrow + 32 * i;
                uint32_t h01, h23, l01, l23;
                uint32_t off = (uint32_t)(r * LDH + quad * 4) * 2;
                split_hilo(avn[i], h01, h23, l01, l23);
                *reinterpret_cast<uint2*>(st + A_HI + off) = make_uint2(h01, h23);
                *reinterpret_cast<uint2*>(st + A_LO + off) = make_uint2(l01, l23);
                split_hilo(bvn[i], h01, h23, l01, l23);
                *reinterpret_cast<uint2*>(st + B_HI + off) = make_uint2(h01, h23);
                *reinterpret_cast<uint2*>(st + B_LO + off) = make_uint2(l01, l23);
            }
        }
        __syncthreads();
    }

    // ---- epilogue: regs -> global, fused bias/relu/mask or raw T ----
    const int rq = lane >> 2;            // 0..7
    const int cq = (lane & 3) * 2;
#pragma unroll
    for (int i = 0; i < 2; i++) {
#pragma unroll
        for (int j = 0; j < 8; j++) {
            int c0 = bn + wn * 64 + j * 8 + cq;
            int r0 = bm + wm * 32 + i * 16 + rq;
            int r1 = r0 + 8;
            float v00 = acc[i][j][0], v01 = acc[i][j][1];
            float v10 = acc[i][j][2], v11 = acc[i][j][3];
            if (c0 < NW) {
                float bb0 = bias[c0], bb1 = bias[c0 + 1];
                v00 = fmaxf(v00 + bb0, 0.f); v01 = fmaxf(v01 + bb1, 0.f);
                v10 = fmaxf(v10 + bb0, 0.f); v11 = fmaxf(v11 + bb1, 0.f);
                if (mask) {
                    float m0 = mask[c0], m1 = mask[c0 + 1];
                    v00 *= m0; v01 *= m1; v10 *= m0; v11 *= m1;
                }
                *reinterpret_cast<float2*>(Xout + (size_t)r0 * NW + c0) =
                    make_float2(v00, v01);
                *reinterpret_cast<float2*>(Xout + (size_t)r1 * NW + c0) =
                    make_float2(v10, v11);
            } else if (c0 < Ntot) {
                int tc = c0 - NW;
                *reinterpret_cast<float2*>(Tout + (size_t)r0 * NT + tc) =
                    make_float2(v00, v01);
                *reinterpret_cast<float2*>(Tout + (size_t)r1 * NT + tc) =
                    make_float2(v10, v11);
            }
        }
    }
}

// ================= small kernels (hebbian path + stats) =================
__device__ __forceinline__ float warp_sum(float v) {
#pragma unroll
    for (int o = 16; o; o >>= 1) v += __shfl_down_sync(0xffffffffu, v, o);
    return v;
}

__global__ void rowstats_kernel(const float* __restrict__ X, int D,
                                float* __restrict__ invn, float* __restrict__ rs) {
    int b = blockIdx.x;
    const float* row = X + (size_t)b * D;
    float s = 0.f, ss = 0.f;
    for (int i = threadIdx.x; i < D; i += blockDim.x) {
        float v = row[i];
        s += v;
        ss = fmaf(v, v, ss);
    }
    __shared__ float shs[8], shss[8];
    s = warp_sum(s);
    ss = warp_sum(ss);
    int w = threadIdx.x >> 5, l = threadIdx.x & 31;
    if (l == 0) { shs[w] = s; shss[w] = ss; }
    __syncthreads();
    if (threadIdx.x == 0) {
        float ts = 0.f, tss = 0.f;
#pragma unroll
        for (int i = 0; i < 8; i++) { ts += shs[i]; tss += shss[i]; }
        invn[b] = rsqrtf(tss);
        rs[b] = ts;
    }
}

__global__ void cb_kernel(const float* __restrict__ T, int Y,
                          const float* __restrict__ invnx, const float* __restrict__ sb,
                          float* __restrict__ cb) {
    int warp = (blockIdx.x * blockDim.x + threadIdx.x) >> 5;
    int lane = threadIdx.x & 31;
    if (warp >= 8192) return;
    const float* row = T + (size_t)warp * Y;
    float ss = 0.f;
    for (int i = lane; i < Y; i += 32) { float v = row[i]; ss = fmaf(v, v, ss); }
    ss = warp_sum(ss);
    if (lane == 0) cb[warp] = sb[warp] * invnx[warp] * rsqrtf(ss);
}

// part[blk, j] = sum_{b in chunk} T[b,j] * c_b ; 256 blocks of 32 rows
__global__ void hebb_kernel(const float* __restrict__ T, int Y,
                            const float* __restrict__ cb, float* __restrict__ part,
                            int rows_per_blk) {
    int j = threadIdx.x;              // blockDim == Y
    int b0 = blockIdx.x * rows_per_blk;
    float acc = 0.f;
    for (int b = b0; b < b0 + rows_per_blk; b++)
        acc = fmaf(T[(size_t)b * Y + j], cb[b], acc);
    part[blockIdx.x * Y + j] = acc;
}

__global__ void rowsum_kernel(const float* __restrict__ H, int Y, int D,
                              float* __restrict__ out) {
    int row = (blockIdx.x * blockDim.x + threadIdx.x) >> 5;
    int lane = threadIdx.x & 31;
    if (row >= Y) return;
    float s = 0.f;
    for (int i = lane; i < D; i += 32) s += H[(size_t)row * D + i];
    s = warp_sum(s);
    if (lane == 0) out[row] = s;
}

__global__ void score_kernel(const float* __restrict__ rsH, const float* __restrict__ part,
                             int Y, float* __restrict__ hm) {
    int j = threadIdx.x;
    float hb = 0.f;
    for (int p = 0; p < 256; p++) hb += part[p * Y + j];
    float theta = 1.0f / (float)Y;
    float sc = fmaf(1.0f - theta, rsH[j], hb);
    __shared__ float smin[256], smax[256];
    smin[j] = sc; smax[j] = sc;
    __syncthreads();
    for (int s = blockDim.x >> 1; s > 0; s >>= 1) {
        if (j < s) {
            smin[j] = fminf(smin[j], smin[j + s]);
            smax[j] = fmaxf(smax[j], smax[j + s]);
        }
        __syncthreads();
    }
    float mn = smin[0], mx = smax[0];
    float norm = (sc - mn) / (mx - mn + 1e-8f);
    hm[j] = (norm < 0.5f) ? 0.0f : 1.0f;
}

// ================= launcher =================
extern "C" void kernel_launch(void* const* d_in, const int* in_sizes, int n_in,
                              void* d_out, int out_size) {
    const float* x     = (const float*)d_in[0];
    const float* mask0 = (const float*)d_in[1];
    const float* mask1 = (const float*)d_in[2];
    const float* mask2 = (const float*)d_in[3];
    const float* W1 = (const float*)d_in[4];
    const float* b1 = (const float*)d_in[5];
    const float* W2 = (const float*)d_in[6];
    const float* b2 = (const float*)d_in[7];
    const float* W3 = (const float*)d_in[8];
    const float* b3 = (const float*)d_in[9];
    const float* W4 = (const float*)d_in[10];
    const float* b4 = (const float*)d_in[11];
    const float* H1 = (const float*)d_in[12];
    const float* H2 = (const float*)d_in[13];
    const float* H3 = (const float*)d_in[14];
    float* out = (float*)d_out;

    float *x1, *x2, *x3, *t, *invnx, *sb, *cb, *part, *rsH;
    cudaGetSymbolAddress((void**)&x1, g_x1);
    cudaGetSymbolAddress((void**)&x2, g_x2);
    cudaGetSymbolAddress((void**)&x3, g_x3);
    cudaGetSymbolAddress((void**)&t,  g_t);
    cudaGetSymbolAddress((void**)&invnx, g_invnx);
    cudaGetSymbolAddress((void**)&sb, g_sb);
    cudaGetSymbolAddress((void**)&cb, g_cb);
    cudaGetSymbolAddress((void**)&part, g_part);
    cudaGetSymbolAddress((void**)&rsH, g_rsH);

    static bool attr_set = false;
    if (!attr_set) {
        cudaFuncSetAttribute(gemm_mma, cudaFuncAttributeMaxDynamicSharedMemorySize,
                             GEMM_SMEM);
        attr_set = true;
    }

    const int B = 8192;
    const size_t OUT_OFF = (size_t)B * 1000;

    // ---- layer 1: x (K=1024) -> x1 (256) + T1 (256) ----
    rowstats_kernel<<<B, 256>>>(x, 1024, invnx, sb);
    gemm_mma<<<dim3(4, B / 128), 256, GEMM_SMEM>>>(x, W1, H1, b1, mask0, x1, t,
                                                   1024, 256, 256);
    cb_kernel<<<B / 8, 256>>>(t, 256, invnx, sb, cb);
    hebb_kernel<<<256, 256>>>(t, 256, cb, part, B / 256);
    rowsum_kernel<<<32, 256>>>(H1, 256, 1024, rsH);
    score_kernel<<<1, 256>>>(rsH, part, 256, out + OUT_OFF);

    // ---- layer 2: x1 (K=256) -> x2 (128) + T2 (128) ----
    rowstats_kernel<<<B, 256>>>(x1, 256, invnx, sb);
    gemm_mma<<<dim3(2, B / 128), 256, GEMM_SMEM>>>(x1, W2, H2, b2, mask1, x2, t,
                                                   256, 128, 128);
    cb_kernel<<<B / 8, 256>>>(t, 128, invnx, sb, cb);
    hebb_kernel<<<256, 128>>>(t, 128, cb, part, B / 256);
    rowsum_kernel<<<16, 256>>>(H2, 128, 256, rsH);
    score_kernel<<<1, 128>>>(rsH, part, 128, out + OUT_OFF + 256);

    // ---- layer 3: x2 (K=128) -> x3 (64) + T3 (64) ----
    rowstats_kernel<<<B, 256>>>(x2, 128, invnx, sb);
    gemm_mma<<<dim3(1, B / 128), 256, GEMM_SMEM>>>(x2, W3, H3, b3, mask2, x3, t,
                                                   128, 64, 64);
    cb_kernel<<<B / 8, 256>>>(t, 64, invnx, sb, cb);
    hebb_kernel<<<256, 64>>>(t, 64, cb, part, B / 256);
    rowsum_kernel<<<8, 256>>>(H3, 64, 128, rsH);
    score_kernel<<<1, 64>>>(rsH, part, 64, out + OUT_OFF + 384);

    // ---- layer 4: x3 (K=64) -> out (1000), relu, no mask, no hebbian ----
    gemm_mma<<<dim3(8, B / 128), 256, GEMM_SMEM>>>(x3, W4, (const float*)nullptr,
                                                   b4, (const float*)nullptr,
                                                   out, (float*)nullptr,
                                                   64, 1000, 0);
}

// round 4
// speedup vs baseline: 3.2814x; 1.1213x over previous
#include <cuda_runtime.h>
#include <cuda_bf16.h>
#include <cstdint>
#include <cstddef>

using bf16 = __nv_bfloat16;

// ================= device scratch (no allocations allowed) =================
__device__ __align__(16) bf16 g_xh [8192 * 1024];
__device__ __align__(16) bf16 g_xl [8192 * 1024];
__device__ __align__(16) bf16 g_x1h[8192 * 256];
__device__ __align__(16) bf16 g_x1l[8192 * 256];
__device__ __align__(16) bf16 g_x2h[8192 * 128];
__device__ __align__(16) bf16 g_x2l[8192 * 128];
__device__ __align__(16) bf16 g_x3h[8192 * 64];
__device__ __align__(16) bf16 g_x3l[8192 * 64];
__device__ __align__(16) bf16 g_B1h[512 * 1024];
__device__ __align__(16) bf16 g_B1l[512 * 1024];
__device__ __align__(16) bf16 g_B2h[256 * 256];
__device__ __align__(16) bf16 g_B2l[256 * 256];
__device__ __align__(16) bf16 g_B3h[128 * 128];
__device__ __align__(16) bf16 g_B3l[128 * 128];
__device__ __align__(16) bf16 g_B4h[1024 * 64];
__device__ __align__(16) bf16 g_B4l[1024 * 64];
__device__ float g_t[8192 * 256];
__device__ float g_invnx[8192];
__device__ float g_sb[8192];
__device__ float g_cb[8192];
__device__ float g_part[256 * 256];
__device__ float g_rsH[512];          // three slots: 0 / 256 / 384

// ================= helpers =================
__device__ __forceinline__ uint32_t smem_u32(const void* p) {
    uint32_t a;
    asm("{ .reg .u64 t; cvta.to.shared.u64 t, %1; cvt.u32.u64 %0, t; }"
        : "=r"(a) : "l"(p));
    return a;
}
__device__ __forceinline__ void ldsm4(uint32_t* r, uint32_t addr) {
    asm volatile("ldmatrix.sync.aligned.m8n8.x4.shared.b16 {%0,%1,%2,%3}, [%4];"
                 : "=r"(r[0]), "=r"(r[1]), "=r"(r[2]), "=r"(r[3]) : "r"(addr));
}
__device__ __forceinline__ void mma16816(float* d, const uint32_t* a, const uint32_t* b) {
    asm volatile(
        "mma.sync.aligned.m16n8k16.row.col.f32.bf16.bf16.f32 "
        "{%0,%1,%2,%3}, {%4,%5,%6,%7}, {%8,%9}, {%0,%1,%2,%3};"
        : "+f"(d[0]), "+f"(d[1]), "+f"(d[2]), "+f"(d[3])
        : "r"(a[0]), "r"(a[1]), "r"(a[2]), "r"(a[3]), "r"(b[0]), "r"(b[1]));
}
__device__ __forceinline__ void cp16(uint32_t dst, const void* src) {
    asm volatile("cp.async.cg.shared.global [%0], [%1], 16;"
                 :: "r"(dst), "l"(src) : "memory");
}
__device__ __forceinline__ void split1(float v, bf16& h, bf16& l) {
    h = __float2bfloat16(v);
    l = __float2bfloat16(v - __bfloat162float(h));
}
__device__ __forceinline__ float warp_sum(float v) {
#pragma unroll
    for (int o = 16; o; o >>= 1) v += __shfl_down_sync(0xffffffffu, v, o);
    return v;
}

// ================= pure-bf16 3-pass pipelined GEMM =================
// acc[m,n] = sum over 3 segments: AhBh + AlBh + AhBl  (A [M,K], B [N,K] hi/lo)
// Epilogue: n<NW: v=relu(acc+bias)*mask -> split -> Xh/Xl  (or fp32 -> Xf)
//           NW<=n<NW+NT: raw fp32 -> Tout
#define LDH     72                      // halfwords per smem row (64 + 8 pad)
#define A_BYTES (128 * LDH * 2)         // 18432
#define STAGE_B (2 * A_BYTES)           // 36864
#define GEMM_SMEM (3 * STAGE_B)         // 110592

__global__ __launch_bounds__(256, 2)
void gemm_mma(const bf16* __restrict__ Ah, const bf16* __restrict__ Al,
              const bf16* __restrict__ Bh, const bf16* __restrict__ Bl,
              const float* __restrict__ bias, const float* __restrict__ mask,
              bf16* __restrict__ Xh, bf16* __restrict__ Xl,
              float* __restrict__ Xf, float* __restrict__ Tout,
              int K, int NW, int NT) {
    extern __shared__ char smem[];
    const uint32_t sbase = smem_u32(smem);
    const int tid = threadIdx.x;
    const int lane = tid & 31;
    const int warp = tid >> 5;
    const int wm = warp >> 1;           // 4 m-slots of 32
    const int wn = warp & 1;            // 2 n-slots of 64
    const int bm = blockIdx.y * 128;
    const int bn = blockIdx.x * 128;
    const int Kd64 = K >> 6;
    const int NC = 3 * Kd64;

    const int row0 = tid >> 3;          // 0..31
    const int cb8 = (tid & 7) * 8;      // 0..56

    float acc[2][8][4];
#pragma unroll
    for (int i = 0; i < 2; i++)
#pragma unroll
        for (int j = 0; j < 8; j++)
#pragma unroll
            for (int q = 0; q < 4; q++) acc[i][j][q] = 0.f;

    // chunk issuer: seg picks pointer pair, k0 within K
    auto issue = [&](int c, int buf) {
        int seg = (c >= 2 * Kd64) ? 2 : ((c >= Kd64) ? 1 : 0);
        int k0 = (c - seg * Kd64) << 6;
        const bf16* Ap = (seg == 1) ? Al : Ah;
        const bf16* Bp = (seg == 2) ? Bl : Bh;
        uint32_t sA = sbase + buf * STAGE_B;
        uint32_t sB = sA + A_BYTES;
#pragma unroll
        for (int i = 0; i < 4; i++) {
            int r = row0 + 32 * i;
            uint32_t off = (uint32_t)(r * LDH + cb8) * 2;
            cp16(sA + off, Ap + (size_t)(bm + r) * K + k0 + cb8);
            cp16(sB + off, Bp + (size_t)(bn + r) * K + k0 + cb8);
        }
    };

    // prologue: fill 3 stages
#pragma unroll
    for (int s = 0; s < 3; s++) {
        if (s < NC) issue(s, s);
        asm volatile("cp.async.commit_group;" ::: "memory");
    }

    const int rl = lane & 15, ka = (lane >> 4) * 8;
    const int sec = lane >> 3;
    const int nloc = ((sec & 2) ? 8 : 0) + (lane & 7);
    const int kb = (sec & 1) * 8;

    for (int c = 0; c < NC; c++) {
        asm volatile("cp.async.wait_group 2;" ::: "memory");
        __syncthreads();
        const uint32_t stb = sbase + (uint32_t)(c % 3) * STAGE_B;
        const uint32_t stbB = stb + A_BYTES;
#pragma unroll
        for (int kk = 0; kk < 64; kk += 16) {
            uint32_t a[2][4];
#pragma unroll
            for (int i = 0; i < 2; i++)
                ldsm4(a[i], stb + (uint32_t)((wm * 32 + i * 16 + rl) * LDH + kk + ka) * 2);
            uint32_t b[8][2];
#pragma unroll
            for (int p = 0; p < 4; p++) {
                uint32_t r4[4];
                ldsm4(r4, stbB + (uint32_t)((wn * 64 + p * 16 + nloc) * LDH + kk + kb) * 2);
                b[2 * p][0] = r4[0]; b[2 * p][1] = r4[1];
                b[2 * p + 1][0] = r4[2]; b[2 * p + 1][1] = r4[3];
            }
#pragma unroll
            for (int i = 0; i < 2; i++)
#pragma unroll
                for (int j = 0; j < 8; j++)
                    mma16816(acc[i][j], a[i], b[j]);
        }
        __syncthreads();
        if (c + 3 < NC) issue(c + 3, (c + 3) % 3);
        asm volatile("cp.async.commit_group;" ::: "memory");
    }

    // ---- epilogue ----
    const int rq = lane >> 2;
    const int cq = (lane & 3) * 2;
    const int Ntot = NW + NT;
#pragma unroll
    for (int i = 0; i < 2; i++) {
        int r0 = bm + wm * 32 + i * 16 + rq;
        int r1 = r0 + 8;
#pragma unroll
        for (int j = 0; j < 8; j++) {
            int c0 = bn + wn * 64 + j * 8 + cq;
            float v00 = acc[i][j][0], v01 = acc[i][j][1];
            float v10 = acc[i][j][2], v11 = acc[i][j][3];
            if (c0 < NW) {
                float bb0 = bias[c0], bb1 = bias[c0 + 1];
                v00 = fmaxf(v00 + bb0, 0.f); v01 = fmaxf(v01 + bb1, 0.f);
                v10 = fmaxf(v10 + bb0, 0.f); v11 = fmaxf(v11 + bb1, 0.f);
                if (mask) {
                    float m0 = mask[c0], m1 = mask[c0 + 1];
                    v00 *= m0; v01 *= m1; v10 *= m0; v11 *= m1;
                }
                if (Xh) {
                    bf16 h, l;
                    __nv_bfloat162 hp, lp;
                    split1(v00, h, l); hp.x = h; lp.x = l;
                    split1(v01, h, l); hp.y = h; lp.y = l;
                    *reinterpret_cast<__nv_bfloat162*>(Xh + (size_t)r0 * NW + c0) = hp;
                    *reinterpret_cast<__nv_bfloat162*>(Xl + (size_t)r0 * NW + c0) = lp;
                    split1(v10, h, l); hp.x = h; lp.x = l;
                    split1(v11, h, l); hp.y = h; lp.y = l;
                    *reinterpret_cast<__nv_bfloat162*>(Xh + (size_t)r1 * NW + c0) = hp;
                    *reinterpret_cast<__nv_bfloat162*>(Xl + (size_t)r1 * NW + c0) = lp;
                } else {
                    *reinterpret_cast<float2*>(Xf + (size_t)r0 * NW + c0) =
                        make_float2(v00, v01);
                    *reinterpret_cast<float2*>(Xf + (size_t)r1 * NW + c0) =
                        make_float2(v10, v11);
                }
            } else if (c0 < Ntot) {
                int tc = c0 - NW;
                *reinterpret_cast<float2*>(Tout + (size_t)r0 * NT + tc) =
                    make_float2(v00, v01);
                *reinterpret_cast<float2*>(Tout + (size_t)r1 * NT + tc) =
                    make_float2(v10, v11);
            }
        }
    }
}

// ================= conversion kernels =================
// 7 segments: W1,H1 -> B1 | W2,H2 -> B2 | W3,H3 -> B3 | W4 -> B4 (padded)
__global__ void split_weights(const float* W1, const float* H1, const float* W2,
                              const float* H2, const float* W3, const float* H3,
                              const float* W4,
                              bf16* B1h, bf16* B1l, bf16* B2h, bf16* B2l,
                              bf16* B3h, bf16* B3l, bf16* B4h, bf16* B4l) {
    const float* src; bf16 *dh, *dl; int n, ntot;
    switch (blockIdx.y) {
        case 0: src = W1; dh = B1h;            dl = B1l;            n = 256*1024; ntot = n; break;
        case 1: src = H1; dh = B1h + 256*1024; dl = B1l + 256*1024; n = 256*1024; ntot = n; break;
        case 2: src = W2; dh = B2h;            dl = B2l;            n = 128*256;  ntot = n; break;
        case 3: src = H2; dh = B2h + 128*256;  dl = B2l + 128*256;  n = 128*256;  ntot = n; break;
        case 4: src = W3; dh = B3h;            dl = B3l;            n = 64*128;   ntot = n; break;
        case 5: src = H3; dh = B3h + 64*128;   dl = B3l + 64*128;   n = 64*128;   ntot = n; break;
        default: src = W4; dh = B4h;           dl = B4l;            n = 1000*64;  ntot = 1024*64; break;
    }
    for (int i = (blockIdx.x * blockDim.x + threadIdx.x) * 4; i < ntot;
         i += gridDim.x * blockDim.x * 4) {
        float4 v;
        if (i + 3 < n) v = *reinterpret_cast<const float4*>(src + i);
        else v = make_float4(i < n ? src[i] : 0.f, i + 1 < n ? src[i + 1] : 0.f,
                             i + 2 < n ? src[i + 2] : 0.f, i + 3 < n ? src[i + 3] : 0.f);
        bf16 h, l;
        __nv_bfloat162 hp0, hp1, lp0, lp1;
        split1(v.x, h, l); hp0.x = h; lp0.x = l;
        split1(v.y, h, l); hp0.y = h; lp0.y = l;
        split1(v.z, h, l); hp1.x = h; lp1.x = l;
        split1(v.w, h, l); hp1.y = h; lp1.y = l;
        reinterpret_cast<__nv_bfloat162*>(dh + i)[0] = hp0;
        reinterpret_cast<__nv_bfloat162*>(dh + i)[1] = hp1;
        reinterpret_cast<__nv_bfloat162*>(dl + i)[0] = lp0;
        reinterpret_cast<__nv_bfloat162*>(dl + i)[1] = lp1;
    }
}

// fused: per-row norm/sum of fp32 x (D=1024) + hi/lo split write
__global__ void rowstats_split(const float* __restrict__ X, float* __restrict__ invn,
                               float* __restrict__ rs, bf16* __restrict__ xh,
                               bf16* __restrict__ xl) {
    int b = blockIdx.x, t = threadIdx.x;   // 256 threads
    const float* row = X + (size_t)b * 1024;
    float4 v = *reinterpret_cast<const float4*>(row + t * 4);
    bf16 h, l;
    __nv_bfloat162 hp0, hp1, lp0, lp1;
    split1(v.x, h, l); hp0.x = h; lp0.x = l;
    split1(v.y, h, l); hp0.y = h; lp0.y = l;
    split1(v.z, h, l); hp1.x = h; lp1.x = l;
    split1(v.w, h, l); hp1.y = h; lp1.y = l;
    size_t o = (size_t)b * 1024 + t * 4;
    reinterpret_cast<__nv_bfloat162*>(xh + o)[0] = hp0;
    reinterpret_cast<__nv_bfloat162*>(xh + o)[1] = hp1;
    reinterpret_cast<__nv_bfloat162*>(xl + o)[0] = lp0;
    reinterpret_cast<__nv_bfloat162*>(xl + o)[1] = lp1;
    float s = v.x + v.y + v.z + v.w;
    float ss = fmaf(v.x, v.x, fmaf(v.y, v.y, fmaf(v.z, v.z, v.w * v.w)));
    __shared__ float shs[8], shss[8];
    s = warp_sum(s); ss = warp_sum(ss);
    int w = t >> 5, lid = t & 31;
    if (lid == 0) { shs[w] = s; shss[w] = ss; }
    __syncthreads();
    if (t == 0) {
        float ts = 0.f, tss = 0.f;
#pragma unroll
        for (int i = 0; i < 8; i++) { ts += shs[i]; tss += shss[i]; }
        invn[b] = rsqrtf(tss);
        rs[b] = ts;
    }
}

// per-row norm/sum from hi/lo bf16 activation
__global__ void rowstats_hl(const bf16* __restrict__ hi, const bf16* __restrict__ lo,
                            int D, float* __restrict__ invn, float* __restrict__ rs) {
    int b = blockIdx.x, t = threadIdx.x;   // 128 threads
    float s = 0.f, ss = 0.f;
    for (int i = t; i < D; i += 128) {
        float v = __bfloat162float(hi[(size_t)b * D + i]) +
                  __bfloat162float(lo[(size_t)b * D + i]);
        s += v;
        ss = fmaf(v, v, ss);
    }
    __shared__ float shs[4], shss[4];
    s = warp_sum(s); ss = warp_sum(ss);
    int w = t >> 5, lid = t & 31;
    if (lid == 0) { shs[w] = s; shss[w] = ss; }
    __syncthreads();
    if (t == 0) {
        float ts = 0.f, tss = 0.f;
#pragma unroll
        for (int i = 0; i < 4; i++) { ts += shs[i]; tss += shss[i]; }
        invn[b] = rsqrtf(tss);
        rs[b] = ts;
    }
}

// ================= hebbian-path kernels =================
__global__ void cb_kernel(const float* __restrict__ T, int Y,
                          const float* __restrict__ invnx, const float* __restrict__ sb,
                          float* __restrict__ cb) {
    int wrp = (blockIdx.x * blockDim.x + threadIdx.x) >> 5;
    int lane = threadIdx.x & 31;
    if (wrp >= 8192) return;
    const float* row = T + (size_t)wrp * Y;
    float ss = 0.f;
    for (int i = lane; i < Y; i += 32) { float v = row[i]; ss = fmaf(v, v, ss); }
    ss = warp_sum(ss);
    if (lane == 0) cb[wrp] = sb[wrp] * invnx[wrp] * rsqrtf(ss);
}

// part[blk, j] = sum over 32 rows of T[b,j]*c_b ; 256 blocks, 4-way ILP
__global__ void hebb_kernel(const float* __restrict__ T, int Y,
                            const float* __restrict__ cb, float* __restrict__ part) {
    int j = threadIdx.x;              // blockDim == Y
    int b0 = blockIdx.x * 32;
    float a0 = 0.f, a1 = 0.f, a2 = 0.f, a3 = 0.f;
#pragma unroll
    for (int b = b0; b < b0 + 32; b += 4) {
        a0 = fmaf(T[(size_t)b * Y + j],       cb[b],     a0);
        a1 = fmaf(T[(size_t)(b + 1) * Y + j], cb[b + 1], a1);
        a2 = fmaf(T[(size_t)(b + 2) * Y + j], cb[b + 2], a2);
        a3 = fmaf(T[(size_t)(b + 3) * Y + j], cb[b + 3], a3);
    }
    part[blockIdx.x * Y + j] = (a0 + a1) + (a2 + a3);
}

__global__ void rowsum_kernel(const float* __restrict__ H, int Y, int D,
                              float* __restrict__ out) {
    int row = (blockIdx.x * blockDim.x + threadIdx.x) >> 5;
    int lane = threadIdx.x & 31;
    if (row >= Y) return;
    float s = 0.f;
    for (int i = lane; i < D; i += 32) s += H[(size_t)row * D + i];
    s = warp_sum(s);
    if (lane == 0) out[row] = s;
}

__global__ void score_kernel(const float* __restrict__ rsH, const float* __restrict__ part,
                             int Y, float* __restrict__ hm) {
    int j = threadIdx.x;
    float hb = 0.f;
    for (int p = 0; p < 256; p++) hb += part[p * Y + j];
    float theta = 1.0f / (float)Y;
    float sc = fmaf(1.0f - theta, rsH[j], hb);
    __shared__ float smin[256], smax[256];
    smin[j] = sc; smax[j] = sc;
    __syncthreads();
    for (int s = blockDim.x >> 1; s > 0; s >>= 1) {
        if (j < s) {
            smin[j] = fminf(smin[j], smin[j + s]);
            smax[j] = fmaxf(smax[j], smax[j + s]);
        }
        __syncthreads();
    }
    float mn = smin[0], mx = smax[0];
    float norm = (sc - mn) / (mx - mn + 1e-8f);
    hm[j] = (norm < 0.5f) ? 0.0f : 1.0f;
}

// ================= launcher =================
extern "C" void kernel_launch(void* const* d_in, const int* in_sizes, int n_in,
                              void* d_out, int out_size) {
    const float* x     = (const float*)d_in[0];
    const float* mask0 = (const float*)d_in[1];
    const float* mask1 = (const float*)d_in[2];
    const float* mask2 = (const float*)d_in[3];
    const float* W1 = (const float*)d_in[4];
    const float* b1 = (const float*)d_in[5];
    const float* W2 = (const float*)d_in[6];
    const float* b2 = (const float*)d_in[7];
    const float* W3 = (const float*)d_in[8];
    const float* b3 = (const float*)d_in[9];
    const float* W4 = (const float*)d_in[10];
    const float* b4 = (const float*)d_in[11];
    const float* H1 = (const float*)d_in[12];
    const float* H2 = (const float*)d_in[13];
    const float* H3 = (const float*)d_in[14];
    float* out = (float*)d_out;

    bf16 *xh, *xl, *x1h, *x1l, *x2h, *x2l, *x3h, *x3l;
    bf16 *B1h, *B1l, *B2h, *B2l, *B3h, *B3l, *B4h, *B4l;
    float *t, *invnx, *sb, *cb, *part, *rsH;
    cudaGetSymbolAddress((void**)&xh, g_xh);   cudaGetSymbolAddress((void**)&xl, g_xl);
    cudaGetSymbolAddress((void**)&x1h, g_x1h); cudaGetSymbolAddress((void**)&x1l, g_x1l);
    cudaGetSymbolAddress((void**)&x2h, g_x2h); cudaGetSymbolAddress((void**)&x2l, g_x2l);
    cudaGetSymbolAddress((void**)&x3h, g_x3h); cudaGetSymbolAddress((void**)&x3l, g_x3l);
    cudaGetSymbolAddress((void**)&B1h, g_B1h); cudaGetSymbolAddress((void**)&B1l, g_B1l);
    cudaGetSymbolAddress((void**)&B2h, g_B2h); cudaGetSymbolAddress((void**)&B2l, g_B2l);
    cudaGetSymbolAddress((void**)&B3h, g_B3h); cudaGetSymbolAddress((void**)&B3l, g_B3l);
    cudaGetSymbolAddress((void**)&B4h, g_B4h); cudaGetSymbolAddress((void**)&B4l, g_B4l);
    cudaGetSymbolAddress((void**)&t, g_t);
    cudaGetSymbolAddress((void**)&invnx, g_invnx);
    cudaGetSymbolAddress((void**)&sb, g_sb);
    cudaGetSymbolAddress((void**)&cb, g_cb);
    cudaGetSymbolAddress((void**)&part, g_part);
    cudaGetSymbolAddress((void**)&rsH, g_rsH);

    static bool attr_set = false;
    if (!attr_set) {
        cudaFuncSetAttribute(gemm_mma, cudaFuncAttributeMaxDynamicSharedMemorySize,
                             GEMM_SMEM);
        attr_set = true;
    }

    const int B = 8192;
    const size_t OUT_OFF = (size_t)B * 1000;

    // ---- input conversions + H rowsums (independent) ----
    split_weights<<<dim3(256, 7), 256>>>(W1, H1, W2, H2, W3, H3, W4,
                                         B1h, B1l, B2h, B2l, B3h, B3l, B4h, B4l);
    rowstats_split<<<B, 256>>>(x, invnx, sb, xh, xl);
    rowsum_kernel<<<32, 256>>>(H1, 256, 1024, rsH);
    rowsum_kernel<<<16, 256>>>(H2, 128, 256, rsH + 256);
    rowsum_kernel<<<8, 256>>>(H3, 64, 128, rsH + 384);

    // ---- layer 1: x (K=1024) -> x1 (256) + T1 (256) ----
    gemm_mma<<<dim3(4, 64), 256, GEMM_SMEM>>>(xh, xl, B1h, B1l, b1, mask0,
                                              x1h, x1l, nullptr, t, 1024, 256, 256);
    cb_kernel<<<1024, 256>>>(t, 256, invnx, sb, cb);
    hebb_kernel<<<256, 256>>>(t, 256, cb, part);
    score_kernel<<<1, 256>>>(rsH, part, 256, out + OUT_OFF);

    // ---- layer 2: x1 (K=256) -> x2 (128) + T2 (128) ----
    rowstats_hl<<<B, 128>>>(x1h, x1l, 256, invnx, sb);
    gemm_mma<<<dim3(2, 64), 256, GEMM_SMEM>>>(x1h, x1l, B2h, B2l, b2, mask1,
                                              x2h, x2l, nullptr, t, 256, 128, 128);
    cb_kernel<<<1024, 256>>>(t, 128, invnx, sb, cb);
    hebb_kernel<<<256, 128>>>(t, 128, cb, part);
    score_kernel<<<1, 128>>>(rsH + 256, part, 128, out + OUT_OFF + 256);

    // ---- layer 3: x2 (K=128) -> x3 (64) + T3 (64) ----
    rowstats_hl<<<B, 128>>>(x2h, x2l, 128, invnx, sb);
    gemm_mma<<<dim3(1, 64), 256, GEMM_SMEM>>>(x2h, x2l, B3h, B3l, b3, mask2,
                                              x3h, x3l, nullptr, t, 128, 64, 64);
    cb_kernel<<<1024, 256>>>(t, 64, invnx, sb, cb);
    hebb_kernel<<<256, 64>>>(t, 64, cb, part);
    score_kernel<<<1, 64>>>(rsH + 384, part, 64, out + OUT_OFF + 384);

    // ---- layer 4: x3 (K=64) -> out (1000 of padded 1024), relu only ----
    gemm_mma<<<dim3(8, 64), 256, GEMM_SMEM>>>(x3h, x3l, B4h, B4l, b4,
                                              (const float*)nullptr,
                                              (bf16*)nullptr, (bf16*)nullptr,
                                              out, (float*)nullptr, 64, 1000, 0);
}

// round 5
// speedup vs baseline: 3.8603x; 1.1764x over previous
#include <cuda_runtime.h>
#include <cuda_bf16.h>
#include <cstdint>
#include <cstddef>

using bf16 = __nv_bfloat16;

// ================= device scratch (no allocations allowed) =================
__device__ __align__(16) bf16 g_xh [8192 * 1024];
__device__ __align__(16) bf16 g_xl [8192 * 1024];
__device__ __align__(16) bf16 g_x1h[8192 * 256];
__device__ __align__(16) bf16 g_x1l[8192 * 256];
__device__ __align__(16) bf16 g_x2h[8192 * 128];
__device__ __align__(16) bf16 g_x2l[8192 * 128];
__device__ __align__(16) bf16 g_x3h[8192 * 64];
__device__ __align__(16) bf16 g_x3l[8192 * 64];
__device__ __align__(16) bf16 g_B1h[512 * 1024];
__device__ __align__(16) bf16 g_B1l[512 * 1024];
__device__ __align__(16) bf16 g_B2h[256 * 256];
__device__ __align__(16) bf16 g_B2l[256 * 256];
__device__ __align__(16) bf16 g_B3h[128 * 128];
__device__ __align__(16) bf16 g_B3l[128 * 128];
__device__ __align__(16) bf16 g_B4h[1024 * 64];
__device__ __align__(16) bf16 g_B4l[1024 * 64];
__device__ float g_t1[8192 * 256];
__device__ float g_t2[8192 * 128];
__device__ float g_t3[8192 * 64];
__device__ float g_invn[3][8192];
__device__ float g_sb[3][8192];
__device__ float g_cb[3][8192];
__device__ float g_part1[256 * 256];
__device__ float g_part2[256 * 128];
__device__ float g_part3[256 * 64];
__device__ float g_rsH[512];          // slots: 0 / 256 / 384

// ================= helpers =================
__device__ __forceinline__ uint32_t smem_u32(const void* p) {
    uint32_t a;
    asm("{ .reg .u64 t; cvta.to.shared.u64 t, %1; cvt.u32.u64 %0, t; }"
        : "=r"(a) : "l"(p));
    return a;
}
__device__ __forceinline__ void ldsm4(uint32_t* r, uint32_t addr) {
    asm volatile("ldmatrix.sync.aligned.m8n8.x4.shared.b16 {%0,%1,%2,%3}, [%4];"
                 : "=r"(r[0]), "=r"(r[1]), "=r"(r[2]), "=r"(r[3]) : "r"(addr));
}
__device__ __forceinline__ void mma16816(float* d, const uint32_t* a, const uint32_t* b) {
    asm volatile(
        "mma.sync.aligned.m16n8k16.row.col.f32.bf16.bf16.f32 "
        "{%0,%1,%2,%3}, {%4,%5,%6,%7}, {%8,%9}, {%0,%1,%2,%3};"
        : "+f"(d[0]), "+f"(d[1]), "+f"(d[2]), "+f"(d[3])
        : "r"(a[0]), "r"(a[1]), "r"(a[2]), "r"(a[3]), "r"(b[0]), "r"(b[1]));
}
__device__ __forceinline__ void cp16(uint32_t dst, const void* src) {
    asm volatile("cp.async.cg.shared.global [%0], [%1], 16;"
                 :: "r"(dst), "l"(src) : "memory");
}
__device__ __forceinline__ void split1(float v, bf16& h, bf16& l) {
    h = __float2bfloat16(v);
    l = __float2bfloat16(v - __bfloat162float(h));
}
__device__ __forceinline__ float warp_sum(float v) {
#pragma unroll
    for (int o = 16; o; o >>= 1) v += __shfl_down_sync(0xffffffffu, v, o);
    return v;
}

// ================= pure-bf16 3-pass pipelined GEMM (unchanged from R4) ======
#define LDH     72
#define A_BYTES (128 * LDH * 2)
#define STAGE_B (2 * A_BYTES)
#define GEMM_SMEM (3 * STAGE_B)

__global__ __launch_bounds__(256, 2)
void gemm_mma(const bf16* __restrict__ Ah, const bf16* __restrict__ Al,
              const bf16* __restrict__ Bh, const bf16* __restrict__ Bl,
              const float* __restrict__ bias, const float* __restrict__ mask,
              bf16* __restrict__ Xh, bf16* __restrict__ Xl,
              float* __restrict__ Xf, float* __restrict__ Tout,
              int K, int NW, int NT) {
    extern __shared__ char smem[];
    const uint32_t sbase = smem_u32(smem);
    const int tid = threadIdx.x;
    const int lane = tid & 31;
    const int warp = tid >> 5;
    const int wm = warp >> 1;
    const int wn = warp & 1;
    const int bm = blockIdx.y * 128;
    const int bn = blockIdx.x * 128;
    const int Kd64 = K >> 6;
    const int NC = 3 * Kd64;

    const int row0 = tid >> 3;
    const int cb8 = (tid & 7) * 8;

    float acc[2][8][4];
#pragma unroll
    for (int i = 0; i < 2; i++)
#pragma unroll
        for (int j = 0; j < 8; j++)
#pragma unroll
            for (int q = 0; q < 4; q++) acc[i][j][q] = 0.f;

    auto issue = [&](int c, int buf) {
        int seg = (c >= 2 * Kd64) ? 2 : ((c >= Kd64) ? 1 : 0);
        int k0 = (c - seg * Kd64) << 6;
        const bf16* Ap = (seg == 1) ? Al : Ah;
        const bf16* Bp = (seg == 2) ? Bl : Bh;
        uint32_t sA = sbase + buf * STAGE_B;
        uint32_t sB = sA + A_BYTES;
#pragma unroll
        for (int i = 0; i < 4; i++) {
            int r = row0 + 32 * i;
            uint32_t off = (uint32_t)(r * LDH + cb8) * 2;
            cp16(sA + off, Ap + (size_t)(bm + r) * K + k0 + cb8);
            cp16(sB + off, Bp + (size_t)(bn + r) * K + k0 + cb8);
        }
    };

#pragma unroll
    for (int s = 0; s < 3; s++) {
        if (s < NC) issue(s, s);
        asm volatile("cp.async.commit_group;" ::: "memory");
    }

    const int rl = lane & 15, ka = (lane >> 4) * 8;
    const int sec = lane >> 3;
    const int nloc = ((sec & 2) ? 8 : 0) + (lane & 7);
    const int kb = (sec & 1) * 8;

    for (int c = 0; c < NC; c++) {
        asm volatile("cp.async.wait_group 2;" ::: "memory");
        __syncthreads();
        const uint32_t stb = sbase + (uint32_t)(c % 3) * STAGE_B;
        const uint32_t stbB = stb + A_BYTES;
#pragma unroll
        for (int kk = 0; kk < 64; kk += 16) {
            uint32_t a[2][4];
#pragma unroll
            for (int i = 0; i < 2; i++)
                ldsm4(a[i], stb + (uint32_t)((wm * 32 + i * 16 + rl) * LDH + kk + ka) * 2);
            uint32_t b[8][2];
#pragma unroll
            for (int p = 0; p < 4; p++) {
                uint32_t r4[4];
                ldsm4(r4, stbB + (uint32_t)((wn * 64 + p * 16 + nloc) * LDH + kk + kb) * 2);
                b[2 * p][0] = r4[0]; b[2 * p][1] = r4[1];
                b[2 * p + 1][0] = r4[2]; b[2 * p + 1][1] = r4[3];
            }
#pragma unroll
            for (int i = 0; i < 2; i++)
#pragma unroll
                for (int j = 0; j < 8; j++)
                    mma16816(acc[i][j], a[i], b[j]);
        }
        __syncthreads();
        if (c + 3 < NC) issue(c + 3, (c + 3) % 3);
        asm volatile("cp.async.commit_group;" ::: "memory");
    }

    const int rq = lane >> 2;
    const int cq = (lane & 3) * 2;
    const int Ntot = NW + NT;
#pragma unroll
    for (int i = 0; i < 2; i++) {
        int r0 = bm + wm * 32 + i * 16 + rq;
        int r1 = r0 + 8;
#pragma unroll
        for (int j = 0; j < 8; j++) {
            int c0 = bn + wn * 64 + j * 8 + cq;
            float v00 = acc[i][j][0], v01 = acc[i][j][1];
            float v10 = acc[i][j][2], v11 = acc[i][j][3];
            if (c0 < NW) {
                float bb0 = bias[c0], bb1 = bias[c0 + 1];
                v00 = fmaxf(v00 + bb0, 0.f); v01 = fmaxf(v01 + bb1, 0.f);
                v10 = fmaxf(v10 + bb0, 0.f); v11 = fmaxf(v11 + bb1, 0.f);
                if (mask) {
                    float m0 = mask[c0], m1 = mask[c0 + 1];
                    v00 *= m0; v01 *= m1; v10 *= m0; v11 *= m1;
                }
                if (Xh) {
                    bf16 h, l;
                    __nv_bfloat162 hp, lp;
                    split1(v00, h, l); hp.x = h; lp.x = l;
                    split1(v01, h, l); hp.y = h; lp.y = l;
                    *reinterpret_cast<__nv_bfloat162*>(Xh + (size_t)r0 * NW + c0) = hp;
                    *reinterpret_cast<__nv_bfloat162*>(Xl + (size_t)r0 * NW + c0) = lp;
                    split1(v10, h, l); hp.x = h; lp.x = l;
                    split1(v11, h, l); hp.y = h; lp.y = l;
                    *reinterpret_cast<__nv_bfloat162*>(Xh + (size_t)r1 * NW + c0) = hp;
                    *reinterpret_cast<__nv_bfloat162*>(Xl + (size_t)r1 * NW + c0) = lp;
                } else {
                    *reinterpret_cast<float2*>(Xf + (size_t)r0 * NW + c0) =
                        make_float2(v00, v01);
                    *reinterpret_cast<float2*>(Xf + (size_t)r1 * NW + c0) =
                        make_float2(v10, v11);
                }
            } else if (c0 < Ntot) {
                int tc = c0 - NW;
                *reinterpret_cast<float2*>(Tout + (size_t)r0 * NT + tc) =
                    make_float2(v00, v01);
                *reinterpret_cast<float2*>(Tout + (size_t)r1 * NT + tc) =
                    make_float2(v10, v11);
            }
        }
    }
}

// ================= conversion kernels =================
__global__ void split_weights(const float* W1, const float* H1, const float* W2,
                              const float* H2, const float* W3, const float* H3,
                              const float* W4,
                              bf16* B1h, bf16* B1l, bf16* B2h, bf16* B2l,
                              bf16* B3h, bf16* B3l, bf16* B4h, bf16* B4l) {
    const float* src; bf16 *dh, *dl; int n, ntot;
    switch (blockIdx.y) {
        case 0: src = W1; dh = B1h;            dl = B1l;            n = 256*1024; ntot = n; break;
        case 1: src = H1; dh = B1h + 256*1024; dl = B1l + 256*1024; n = 256*1024; ntot = n; break;
        case 2: src = W2; dh = B2h;            dl = B2l;            n = 128*256;  ntot = n; break;
        case 3: src = H2; dh = B2h + 128*256;  dl = B2l + 128*256;  n = 128*256;  ntot = n; break;
        case 4: src = W3; dh = B3h;            dl = B3l;            n = 64*128;   ntot = n; break;
        case 5: src = H3; dh = B3h + 64*128;   dl = B3l + 64*128;   n = 64*128;   ntot = n; break;
        default: src = W4; dh = B4h;           dl = B4l;            n = 1000*64;  ntot = 1024*64; break;
    }
    for (int i = (blockIdx.x * blockDim.x + threadIdx.x) * 4; i < ntot;
         i += gridDim.x * blockDim.x * 4) {
        float4 v;
        if (i + 3 < n) v = *reinterpret_cast<const float4*>(src + i);
        else v = make_float4(i < n ? src[i] : 0.f, i + 1 < n ? src[i + 1] : 0.f,
                             i + 2 < n ? src[i + 2] : 0.f, i + 3 < n ? src[i + 3] : 0.f);
        bf16 h, l;
        __nv_bfloat162 hp0, hp1, lp0, lp1;
        split1(v.x, h, l); hp0.x = h; lp0.x = l;
        split1(v.y, h, l); hp0.y = h; lp0.y = l;
        split1(v.z, h, l); hp1.x = h; lp1.x = l;
        split1(v.w, h, l); hp1.y = h; lp1.y = l;
        reinterpret_cast<__nv_bfloat162*>(dh + i)[0] = hp0;
        reinterpret_cast<__nv_bfloat162*>(dh + i)[1] = hp1;
        reinterpret_cast<__nv_bfloat162*>(dl + i)[0] = lp0;
        reinterpret_cast<__nv_bfloat162*>(dl + i)[1] = lp1;
    }
}

__global__ void rowstats_split(const float* __restrict__ X, float* __restrict__ invn,
                               float* __restrict__ rs, bf16* __restrict__ xh,
                               bf16* __restrict__ xl) {
    int b = blockIdx.x, t = threadIdx.x;   // 256 threads
    const float* row = X + (size_t)b * 1024;
    float4 v = *reinterpret_cast<const float4*>(row + t * 4);
    bf16 h, l;
    __nv_bfloat162 hp0, hp1, lp0, lp1;
    split1(v.x, h, l); hp0.x = h; lp0.x = l;
    split1(v.y, h, l); hp0.y = h; lp0.y = l;
    split1(v.z, h, l); hp1.x = h; lp1.x = l;
    split1(v.w, h, l); hp1.y = h; lp1.y = l;
    size_t o = (size_t)b * 1024 + t * 4;
    reinterpret_cast<__nv_bfloat162*>(xh + o)[0] = hp0;
    reinterpret_cast<__nv_bfloat162*>(xh + o)[1] = hp1;
    reinterpret_cast<__nv_bfloat162*>(xl + o)[0] = lp0;
    reinterpret_cast<__nv_bfloat162*>(xl + o)[1] = lp1;
    float s = v.x + v.y + v.z + v.w;
    float ss = fmaf(v.x, v.x, fmaf(v.y, v.y, fmaf(v.z, v.z, v.w * v.w)));
    __shared__ float shs[8], shss[8];
    s = warp_sum(s); ss = warp_sum(ss);
    int w = t >> 5, lid = t & 31;
    if (lid == 0) { shs[w] = s; shss[w] = ss; }
    __syncthreads();
    if (t == 0) {
        float ts = 0.f, tss = 0.f;
#pragma unroll
        for (int i = 0; i < 8; i++) { ts += shs[i]; tss += shss[i]; }
        invn[b] = rsqrtf(tss);
        rs[b] = ts;
    }
}

__global__ void rowstats_hl(const bf16* __restrict__ hi, const bf16* __restrict__ lo,
                            int D, float* __restrict__ invn, float* __restrict__ rs) {
    int b = blockIdx.x, t = threadIdx.x;   // 128 threads
    float s = 0.f, ss = 0.f;
    for (int i = t; i < D; i += 128) {
        float v = __bfloat162float(hi[(size_t)b * D + i]) +
                  __bfloat162float(lo[(size_t)b * D + i]);
        s += v;
        ss = fmaf(v, v, ss);
    }
    __shared__ float shs[4], shss[4];
    s = warp_sum(s); ss = warp_sum(ss);
    int w = t >> 5, lid = t & 31;
    if (lid == 0) { shs[w] = s; shss[w] = ss; }
    __syncthreads();
    if (t == 0) {
        float ts = 0.f, tss = 0.f;
#pragma unroll
        for (int i = 0; i < 4; i++) { ts += shs[i]; tss += shss[i]; }
        invn[b] = rsqrtf(tss);
        rs[b] = ts;
    }
}

// ================= hebbian-path kernels =================
__global__ void cb_kernel(const float* __restrict__ T, int Y,
                          const float* __restrict__ invnx, const float* __restrict__ sb,
                          float* __restrict__ cb) {
    int wrp = (blockIdx.x * blockDim.x + threadIdx.x) >> 5;
    int lane = threadIdx.x & 31;
    if (wrp >= 8192) return;
    const float* row = T + (size_t)wrp * Y;
    float ss = 0.f;
    for (int i = lane; i < Y; i += 32) { float v = row[i]; ss = fmaf(v, v, ss); }
    ss = warp_sum(ss);
    if (lane == 0) cb[wrp] = sb[wrp] * invnx[wrp] * rsqrtf(ss);
}

__global__ void hebb_kernel(const float* __restrict__ T, int Y,
                            const float* __restrict__ cb, float* __restrict__ part) {
    int j = threadIdx.x;
    int b0 = blockIdx.x * 32;
    float a0 = 0.f, a1 = 0.f, a2 = 0.f, a3 = 0.f;
#pragma unroll
    for (int b = b0; b < b0 + 32; b += 4) {
        a0 = fmaf(T[(size_t)b * Y + j],       cb[b],     a0);
        a1 = fmaf(T[(size_t)(b + 1) * Y + j], cb[b + 1], a1);
        a2 = fmaf(T[(size_t)(b + 2) * Y + j], cb[b + 2], a2);
        a3 = fmaf(T[(size_t)(b + 3) * Y + j], cb[b + 3], a3);
    }
    part[blockIdx.x * Y + j] = (a0 + a1) + (a2 + a3);
}

// one block per row
__global__ void rowsum_kernel(const float* __restrict__ H, int D,
                              float* __restrict__ out) {
    int row = blockIdx.x, t = threadIdx.x;   // 128 threads
    float s = 0.f;
    for (int i = t; i < D; i += 128) s += H[(size_t)row * D + i];
    __shared__ float sh[4];
    s = warp_sum(s);
    if ((t & 31) == 0) sh[t >> 5] = s;
    __syncthreads();
    if (t == 0) out[row] = sh[0] + sh[1] + sh[2] + sh[3];
}

__global__ void score_kernel(const float* __restrict__ rsH, const float* __restrict__ part,
                             int Y, float* __restrict__ hm) {
    int j = threadIdx.x;
    float hb = 0.f;
    for (int p = 0; p < 256; p++) hb += part[p * Y + j];
    float theta = 1.0f / (float)Y;
    float sc = fmaf(1.0f - theta, rsH[j], hb);
    __shared__ float smin[256], smax[256];
    smin[j] = sc; smax[j] = sc;
    __syncthreads();
    for (int s = blockDim.x >> 1; s > 0; s >>= 1) {
        if (j < s) {
            smin[j] = fminf(smin[j], smin[j + s]);
            smax[j] = fmaxf(smax[j], smax[j + s]);
        }
        __syncthreads();
    }
    float mn = smin[0], mx = smax[0];
    float norm = (sc - mn) / (mx - mn + 1e-8f);
    hm[j] = (norm < 0.5f) ? 0.0f : 1.0f;
}

// ================= launcher =================
extern "C" void kernel_launch(void* const* d_in, const int* in_sizes, int n_in,
                              void* d_out, int out_size) {
    const float* x     = (const float*)d_in[0];
    const float* mask0 = (const float*)d_in[1];
    const float* mask1 = (const float*)d_in[2];
    const float* mask2 = (const float*)d_in[3];
    const float* W1 = (const float*)d_in[4];
    const float* b1 = (const float*)d_in[5];
    const float* W2 = (const float*)d_in[6];
    const float* b2 = (const float*)d_in[7];
    const float* W3 = (const float*)d_in[8];
    const float* b3 = (const float*)d_in[9];
    const float* W4 = (const float*)d_in[10];
    const float* b4 = (const float*)d_in[11];
    const float* H1 = (const float*)d_in[12];
    const float* H2 = (const float*)d_in[13];
    const float* H3 = (const float*)d_in[14];
    float* out = (float*)d_out;

    bf16 *xh, *xl, *x1h, *x1l, *x2h, *x2l, *x3h, *x3l;
    bf16 *B1h, *B1l, *B2h, *B2l, *B3h, *B3l, *B4h, *B4l;
    float *t1, *t2, *t3, *invn, *sbp, *cbp, *part1, *part2, *part3, *rsH;
    cudaGetSymbolAddress((void**)&xh, g_xh);   cudaGetSymbolAddress((void**)&xl, g_xl);
    cudaGetSymbolAddress((void**)&x1h, g_x1h); cudaGetSymbolAddress((void**)&x1l, g_x1l);
    cudaGetSymbolAddress((void**)&x2h, g_x2h); cudaGetSymbolAddress((void**)&x2l, g_x2l);
    cudaGetSymbolAddress((void**)&x3h, g_x3h); cudaGetSymbolAddress((void**)&x3l, g_x3l);
    cudaGetSymbolAddress((void**)&B1h, g_B1h); cudaGetSymbolAddress((void**)&B1l, g_B1l);
    cudaGetSymbolAddress((void**)&B2h, g_B2h); cudaGetSymbolAddress((void**)&B2l, g_B2l);
    cudaGetSymbolAddress((void**)&B3h, g_B3h); cudaGetSymbolAddress((void**)&B3l, g_B3l);
    cudaGetSymbolAddress((void**)&B4h, g_B4h); cudaGetSymbolAddress((void**)&B4l, g_B4l);
    cudaGetSymbolAddress((void**)&t1, g_t1);
    cudaGetSymbolAddress((void**)&t2, g_t2);
    cudaGetSymbolAddress((void**)&t3, g_t3);
    cudaGetSymbolAddress((void**)&invn, g_invn);
    cudaGetSymbolAddress((void**)&sbp, g_sb);
    cudaGetSymbolAddress((void**)&cbp, g_cb);
    cudaGetSymbolAddress((void**)&part1, g_part1);
    cudaGetSymbolAddress((void**)&part2, g_part2);
    cudaGetSymbolAddress((void**)&part3, g_part3);
    cudaGetSymbolAddress((void**)&rsH, g_rsH);

    float* invn1 = invn;        float* invn2 = invn + 8192;  float* invn3 = invn + 16384;
    float* sb1 = sbp;           float* sb2 = sbp + 8192;     float* sb3 = sbp + 16384;
    float* cb1 = cbp;           float* cb2 = cbp + 8192;     float* cb3 = cbp + 16384;

    static bool inited = false;
    static cudaStream_t s1, s2, s3;
    static cudaEvent_t eFork, eW, eR, eG1, eG2, eG3, eS1, eS2, eS3;
    if (!inited) {
        cudaFuncSetAttribute(gemm_mma, cudaFuncAttributeMaxDynamicSharedMemorySize,
                             GEMM_SMEM);
        cudaStreamCreateWithFlags(&s1, cudaStreamNonBlocking);
        cudaStreamCreateWithFlags(&s2, cudaStreamNonBlocking);
        cudaStreamCreateWithFlags(&s3, cudaStreamNonBlocking);
        cudaEventCreateWithFlags(&eFork, cudaEventDisableTiming);
        cudaEventCreateWithFlags(&eW, cudaEventDisableTiming);
        cudaEventCreateWithFlags(&eR, cudaEventDisableTiming);
        cudaEventCreateWithFlags(&eG1, cudaEventDisableTiming);
        cudaEventCreateWithFlags(&eG2, cudaEventDisableTiming);
        cudaEventCreateWithFlags(&eG3, cudaEventDisableTiming);
        cudaEventCreateWithFlags(&eS1, cudaEventDisableTiming);
        cudaEventCreateWithFlags(&eS2, cudaEventDisableTiming);
        cudaEventCreateWithFlags(&eS3, cudaEventDisableTiming);
        inited = true;
    }

    const int B = 8192;
    const size_t OUT_OFF = (size_t)B * 1000;

    // ---- fork side streams off the capture stream ----
    cudaEventRecord(eFork, 0);
    cudaStreamWaitEvent(s1, eFork, 0);
    cudaStreamWaitEvent(s2, eFork, 0);
    cudaStreamWaitEvent(s3, eFork, 0);

    // s1: weight conversion (gemm1 gate)
    split_weights<<<dim3(256, 7), 256, 0, s1>>>(W1, H1, W2, H2, W3, H3, W4,
                                                B1h, B1l, B2h, B2l, B3h, B3l,
                                                B4h, B4l);
    cudaEventRecord(eW, s1);

    // s2: H rowsums (score gates)
    rowsum_kernel<<<256, 128, 0, s2>>>(H1, 1024, rsH);
    rowsum_kernel<<<128, 128, 0, s2>>>(H2, 256, rsH + 256);
    rowsum_kernel<<<64, 128, 0, s2>>>(H3, 128, rsH + 384);
    cudaEventRecord(eR, s2);

    // s0: x conversion + stats
    rowstats_split<<<B, 256>>>(x, invn1, sb1, xh, xl);

    // ---- layer 1 GEMM on s0 ----
    cudaStreamWaitEvent(0, eW, 0);
    gemm_mma<<<dim3(4, 64), 256, GEMM_SMEM>>>(xh, xl, B1h, B1l, b1, mask0,
                                              x1h, x1l, nullptr, t1, 1024, 256, 256);
    cudaEventRecord(eG1, 0);

    // layer-1 hebb chain on s1 (overlaps gemm2..4)
    cudaStreamWaitEvent(s1, eG1, 0);
    cudaStreamWaitEvent(s1, eR, 0);
    cb_kernel<<<1024, 256, 0, s1>>>(t1, 256, invn1, sb1, cb1);
    hebb_kernel<<<256, 256, 0, s1>>>(t1, 256, cb1, part1);
    score_kernel<<<1, 256, 0, s1>>>(rsH, part1, 256, out + OUT_OFF);
    cudaEventRecord(eS1, s1);

    // ---- layer 2 on s0 ----
    rowstats_hl<<<B, 128>>>(x1h, x1l, 256, invn2, sb2);
    gemm_mma<<<dim3(2, 64), 256, GEMM_SMEM>>>(x1h, x1l, B2h, B2l, b2, mask1,
                                              x2h, x2l, nullptr, t2, 256, 128, 128);
    cudaEventRecord(eG2, 0);

    // layer-2 hebb chain on s2 (already ordered after rowsums on s2)
    cudaStreamWaitEvent(s2, eG2, 0);
    cb_kernel<<<1024, 256, 0, s2>>>(t2, 128, invn2, sb2, cb2);
    hebb_kernel<<<256, 128, 0, s2>>>(t2, 128, cb2, part2);
    score_kernel<<<1, 128, 0, s2>>>(rsH + 256, part2, 128, out + OUT_OFF + 256);
    cudaEventRecord(eS2, s2);

    // ---- layer 3 on s0 ----
    rowstats_hl<<<B, 128>>>(x2h, x2l, 128, invn3, sb3);
    gemm_mma<<<dim3(1, 64), 256, GEMM_SMEM>>>(x2h, x2l, B3h, B3l, b3, mask2,
                                              x3h, x3l, nullptr, t3, 128, 64, 64);
    cudaEventRecord(eG3, 0);

    // layer-3 hebb chain on s3
    cudaStreamWaitEvent(s3, eG3, 0);
    cudaStreamWaitEvent(s3, eR, 0);
    cb_kernel<<<1024, 256, 0, s3>>>(t3, 64, invn3, sb3, cb3);
    hebb_kernel<<<256, 64, 0, s3>>>(t3, 64, cb3, part3);
    score_kernel<<<1, 64, 0, s3>>>(rsH + 384, part3, 64, out + OUT_OFF + 384);
    cudaEventRecord(eS3, s3);

    // ---- layer 4 on s0 ----
    gemm_mma<<<dim3(8, 64), 256, GEMM_SMEM>>>(x3h, x3l, B4h, B4l, b4,
                                              (const float*)nullptr,
                                              (bf16*)nullptr, (bf16*)nullptr,
                                              out, (float*)nullptr, 64, 1000, 0);

    // ---- join ----
    cudaStreamWaitEvent(0, eS1, 0);
    cudaStreamWaitEvent(0, eS2, 0);
    cudaStreamWaitEvent(0, eS3, 0);
}

// round 6
// speedup vs baseline: 4.2091x; 1.0904x over previous
#include <cuda_runtime.h>
#include <cuda_bf16.h>
#include <cstdint>
#include <cstddef>

using bf16 = __nv_bfloat16;

// ================= device scratch (no allocations allowed) =================
__device__ __align__(16) bf16 g_xh [8192 * 1024];
__device__ __align__(16) bf16 g_xl [8192 * 1024];
__device__ __align__(16) bf16 g_x1h[8192 * 256];
__device__ __align__(16) bf16 g_x1l[8192 * 256];
__device__ __align__(16) bf16 g_x2h[8192 * 128];
__device__ __align__(16) bf16 g_x2l[8192 * 128];
__device__ __align__(16) bf16 g_x3h[8192 * 64];
__device__ __align__(16) bf16 g_x3l[8192 * 64];
__device__ __align__(16) bf16 g_B1h[512 * 1024];
__device__ __align__(16) bf16 g_B1l[512 * 1024];
__device__ __align__(16) bf16 g_B2h[256 * 256];
__device__ __align__(16) bf16 g_B2l[256 * 256];
__device__ __align__(16) bf16 g_B3h[128 * 128];
__device__ __align__(16) bf16 g_B3l[128 * 128];
__device__ __align__(16) bf16 g_B4h[1024 * 64];
__device__ __align__(16) bf16 g_B4l[1024 * 64];
__device__ float g_t1[8192 * 256];
__device__ float g_t2[8192 * 128];
__device__ float g_t3[8192 * 64];
__device__ float g_invn[3][8192];
__device__ float g_sb[3][8192];
__device__ float g_cb[3][8192];
__device__ float g_part1[256 * 256];
__device__ float g_part2[256 * 128];
__device__ float g_part3[256 * 64];
__device__ float g_rsH[512];          // slots: 0 / 256 / 384

// ================= helpers =================
__device__ __forceinline__ uint32_t smem_u32(const void* p) {
    uint32_t a;
    asm("{ .reg .u64 t; cvta.to.shared.u64 t, %1; cvt.u32.u64 %0, t; }"
        : "=r"(a) : "l"(p));
    return a;
}
__device__ __forceinline__ void ldsm4(uint32_t* r, uint32_t addr) {
    asm volatile("ldmatrix.sync.aligned.m8n8.x4.shared.b16 {%0,%1,%2,%3}, [%4];"
                 : "=r"(r[0]), "=r"(r[1]), "=r"(r[2]), "=r"(r[3]) : "r"(addr));
}
__device__ __forceinline__ void mma16816(float* d, const uint32_t* a, const uint32_t* b) {
    asm volatile(
        "mma.sync.aligned.m16n8k16.row.col.f32.bf16.bf16.f32 "
        "{%0,%1,%2,%3}, {%4,%5,%6,%7}, {%8,%9}, {%0,%1,%2,%3};"
        : "+f"(d[0]), "+f"(d[1]), "+f"(d[2]), "+f"(d[3])
        : "r"(a[0]), "r"(a[1]), "r"(a[2]), "r"(a[3]), "r"(b[0]), "r"(b[1]));
}
__device__ __forceinline__ void cp16(uint32_t dst, const void* src) {
    asm volatile("cp.async.cg.shared.global [%0], [%1], 16;"
                 :: "r"(dst), "l"(src) : "memory");
}
__device__ __forceinline__ void split1(float v, bf16& h, bf16& l) {
    h = __float2bfloat16(v);
    l = __float2bfloat16(v - __bfloat162float(h));
}
__device__ __forceinline__ float warp_sum(float v) {
#pragma unroll
    for (int o = 16; o; o >>= 1) v += __shfl_down_sync(0xffffffffu, v, o);
    return v;
}

// ================= pure-bf16 3-pass GEMM, 4-tiles-per-chunk =================
// Per K-chunk of 32: stage Ah, Al, Bh, Bl once; run AhBh + AlBh + AhBl from regs.
#define LDH2    40                      // halfwords per row (32 + 8 pad)
#define TILE_B2 (128 * LDH2 * 2)        // 10240
#define STG     (4 * TILE_B2)           // 40960
#define GEMM_SMEM (2 * STG)             // 81920

__global__ __launch_bounds__(256, 2)
void gemm_mma(const bf16* __restrict__ Ah, const bf16* __restrict__ Al,
              const bf16* __restrict__ Bh, const bf16* __restrict__ Bl,
              const float* __restrict__ bias, const float* __restrict__ mask,
              bf16* __restrict__ Xh, bf16* __restrict__ Xl,
              float* __restrict__ Xf, float* __restrict__ Tout,
              int K, int NW, int NT) {
    extern __shared__ char smem[];
    const uint32_t sbase = smem_u32(smem);
    const int tid = threadIdx.x;
    const int lane = tid & 31;
    const int warp = tid >> 5;
    const int wm = warp >> 1;
    const int wn = warp & 1;
    const int bm = blockIdx.y * 128;
    const int bn = blockIdx.x * 128;
    const int NC = K >> 5;

    const int row8 = tid >> 2;          // 0..63
    const int q8 = (tid & 3) * 8;       // element offset 0/8/16/24

    float acc[2][8][4];
#pragma unroll
    for (int i = 0; i < 2; i++)
#pragma unroll
        for (int j = 0; j < 8; j++)
#pragma unroll
            for (int q = 0; q < 4; q++) acc[i][j][q] = 0.f;

    auto issue = [&](int c, int buf) {
        int k0 = c << 5;
        uint32_t st = sbase + buf * STG;
#pragma unroll
        for (int i = 0; i < 2; i++) {
            int r = row8 + 64 * i;
            uint32_t off = (uint32_t)(r * LDH2 + q8) * 2;
            const size_t ao = (size_t)(bm + r) * K + k0 + q8;
            const size_t bo = (size_t)(bn + r) * K + k0 + q8;
            cp16(st + off, Ah + ao);
            cp16(st + TILE_B2 + off, Al + ao);
            cp16(st + 2 * TILE_B2 + off, Bh + bo);
            cp16(st + 3 * TILE_B2 + off, Bl + bo);
        }
    };

#pragma unroll
    for (int s = 0; s < 2; s++) {
        if (s < NC) issue(s, s);
        asm volatile("cp.async.commit_group;" ::: "memory");
    }

    const int rl = lane & 15, ka = (lane >> 4) * 8;
    const int sec = lane >> 3;
    const int nloc = ((sec & 2) ? 8 : 0) + (lane & 7);
    const int kb = (sec & 1) * 8;

    for (int c = 0; c < NC; c++) {
        asm volatile("cp.async.wait_group 1;" ::: "memory");
        __syncthreads();
        const uint32_t stb = sbase + (uint32_t)(c & 1) * STG;
#pragma unroll
        for (int kk = 0; kk < 32; kk += 16) {
            uint32_t ah[2][4], al[2][4];
#pragma unroll
            for (int i = 0; i < 2; i++) {
                uint32_t off = (uint32_t)((wm * 32 + i * 16 + rl) * LDH2 + kk + ka) * 2;
                ldsm4(ah[i], stb + off);
                ldsm4(al[i], stb + TILE_B2 + off);
            }
            uint32_t b[8][2];
            // --- Bh pass(es) ---
#pragma unroll
            for (int p = 0; p < 4; p++) {
                uint32_t r4[4];
                ldsm4(r4, stb + 2 * TILE_B2 +
                          (uint32_t)((wn * 64 + p * 16 + nloc) * LDH2 + kk + kb) * 2);
                b[2 * p][0] = r4[0]; b[2 * p][1] = r4[1];
                b[2 * p + 1][0] = r4[2]; b[2 * p + 1][1] = r4[3];
            }
#pragma unroll
            for (int i = 0; i < 2; i++)
#pragma unroll
                for (int j = 0; j < 8; j++) {
                    mma16816(acc[i][j], ah[i], b[j]);
                    mma16816(acc[i][j], al[i], b[j]);
                }
            // --- Bl pass (reuse b regs) ---
#pragma unroll
            for (int p = 0; p < 4; p++) {
                uint32_t r4[4];
                ldsm4(r4, stb + 3 * TILE_B2 +
                          (uint32_t)((wn * 64 + p * 16 + nloc) * LDH2 + kk + kb) * 2);
                b[2 * p][0] = r4[0]; b[2 * p][1] = r4[1];
                b[2 * p + 1][0] = r4[2]; b[2 * p + 1][1] = r4[3];
            }
#pragma unroll
            for (int i = 0; i < 2; i++)
#pragma unroll
                for (int j = 0; j < 8; j++)
                    mma16816(acc[i][j], ah[i], b[j]);
        }
        __syncthreads();
        if (c + 2 < NC) issue(c + 2, (c + 2) & 1);
        asm volatile("cp.async.commit_group;" ::: "memory");
    }

    // ---- epilogue ----
    const int rq = lane >> 2;
    const int cq = (lane & 3) * 2;
    const int Ntot = NW + NT;
#pragma unroll
    for (int i = 0; i < 2; i++) {
        int r0 = bm + wm * 32 + i * 16 + rq;
        int r1 = r0 + 8;
#pragma unroll
        for (int j = 0; j < 8; j++) {
            int c0 = bn + wn * 64 + j * 8 + cq;
            float v00 = acc[i][j][0], v01 = acc[i][j][1];
            float v10 = acc[i][j][2], v11 = acc[i][j][3];
            if (c0 < NW) {
                float bb0 = bias[c0], bb1 = bias[c0 + 1];
                v00 = fmaxf(v00 + bb0, 0.f); v01 = fmaxf(v01 + bb1, 0.f);
                v10 = fmaxf(v10 + bb0, 0.f); v11 = fmaxf(v11 + bb1, 0.f);
                if (mask) {
                    float m0 = mask[c0], m1 = mask[c0 + 1];
                    v00 *= m0; v01 *= m1; v10 *= m0; v11 *= m1;
                }
                if (Xh) {
                    bf16 h, l;
                    __nv_bfloat162 hp, lp;
                    split1(v00, h, l); hp.x = h; lp.x = l;
                    split1(v01, h, l); hp.y = h; lp.y = l;
                    *reinterpret_cast<__nv_bfloat162*>(Xh + (size_t)r0 * NW + c0) = hp;
                    *reinterpret_cast<__nv_bfloat162*>(Xl + (size_t)r0 * NW + c0) = lp;
                    split1(v10, h, l); hp.x = h; lp.x = l;
                    split1(v11, h, l); hp.y = h; lp.y = l;
                    *reinterpret_cast<__nv_bfloat162*>(Xh + (size_t)r1 * NW + c0) = hp;
                    *reinterpret_cast<__nv_bfloat162*>(Xl + (size_t)r1 * NW + c0) = lp;
                } else {
                    *reinterpret_cast<float2*>(Xf + (size_t)r0 * NW + c0) =
                        make_float2(v00, v01);
                    *reinterpret_cast<float2*>(Xf + (size_t)r1 * NW + c0) =
                        make_float2(v10, v11);
                }
            } else if (c0 < Ntot) {
                int tc = c0 - NW;
                *reinterpret_cast<float2*>(Tout + (size_t)r0 * NT + tc) =
                    make_float2(v00, v01);
                *reinterpret_cast<float2*>(Tout + (size_t)r1 * NT + tc) =
                    make_float2(v10, v11);
            }
        }
    }
}

// ================= conversion kernels =================
__global__ void split_weights(const float* W1, const float* H1, const float* W2,
                              const float* H2, const float* W3, const float* H3,
                              const float* W4,
                              bf16* B1h, bf16* B1l, bf16* B2h, bf16* B2l,
                              bf16* B3h, bf16* B3l, bf16* B4h, bf16* B4l) {
    const float* src; bf16 *dh, *dl; int n, ntot;
    switch (blockIdx.y) {
        case 0: src = W1; dh = B1h;            dl = B1l;            n = 256*1024; ntot = n; break;
        case 1: src = H1; dh = B1h + 256*1024; dl = B1l + 256*1024; n = 256*1024; ntot = n; break;
        case 2: src = W2; dh = B2h;            dl = B2l;            n = 128*256;  ntot = n; break;
        case 3: src = H2; dh = B2h + 128*256;  dl = B2l + 128*256;  n = 128*256;  ntot = n; break;
        case 4: src = W3; dh = B3h;            dl = B3l;            n = 64*128;   ntot = n; break;
        case 5: src = H3; dh = B3h + 64*128;   dl = B3l + 64*128;   n = 64*128;   ntot = n; break;
        default: src = W4; dh = B4h;           dl = B4l;            n = 1000*64;  ntot = 1024*64; break;
    }
    for (int i = (blockIdx.x * blockDim.x + threadIdx.x) * 4; i < ntot;
         i += gridDim.x * blockDim.x * 4) {
        float4 v;
        if (i + 3 < n) v = *reinterpret_cast<const float4*>(src + i);
        else v = make_float4(i < n ? src[i] : 0.f, i + 1 < n ? src[i + 1] : 0.f,
                             i + 2 < n ? src[i + 2] : 0.f, i + 3 < n ? src[i + 3] : 0.f);
        bf16 h, l;
        __nv_bfloat162 hp0, hp1, lp0, lp1;
        split1(v.x, h, l); hp0.x = h; lp0.x = l;
        split1(v.y, h, l); hp0.y = h; lp0.y = l;
        split1(v.z, h, l); hp1.x = h; lp1.x = l;
        split1(v.w, h, l); hp1.y = h; lp1.y = l;
        reinterpret_cast<__nv_bfloat162*>(dh + i)[0] = hp0;
        reinterpret_cast<__nv_bfloat162*>(dh + i)[1] = hp1;
        reinterpret_cast<__nv_bfloat162*>(dl + i)[0] = lp0;
        reinterpret_cast<__nv_bfloat162*>(dl + i)[1] = lp1;
    }
}

__global__ void rowstats_split(const float* __restrict__ X, float* __restrict__ invn,
                               float* __restrict__ rs, bf16* __restrict__ xh,
                               bf16* __restrict__ xl) {
    int b = blockIdx.x, t = threadIdx.x;   // 256 threads
    const float* row = X + (size_t)b * 1024;
    float4 v = *reinterpret_cast<const float4*>(row + t * 4);
    bf16 h, l;
    __nv_bfloat162 hp0, hp1, lp0, lp1;
    split1(v.x, h, l); hp0.x = h; lp0.x = l;
    split1(v.y, h, l); hp0.y = h; lp0.y = l;
    split1(v.z, h, l); hp1.x = h; lp1.x = l;
    split1(v.w, h, l); hp1.y = h; lp1.y = l;
    size_t o = (size_t)b * 1024 + t * 4;
    reinterpret_cast<__nv_bfloat162*>(xh + o)[0] = hp0;
    reinterpret_cast<__nv_bfloat162*>(xh + o)[1] = hp1;
    reinterpret_cast<__nv_bfloat162*>(xl + o)[0] = lp0;
    reinterpret_cast<__nv_bfloat162*>(xl + o)[1] = lp1;
    float s = v.x + v.y + v.z + v.w;
    float ss = fmaf(v.x, v.x, fmaf(v.y, v.y, fmaf(v.z, v.z, v.w * v.w)));
    __shared__ float shs[8], shss[8];
    s = warp_sum(s); ss = warp_sum(ss);
    int w = t >> 5, lid = t & 31;
    if (lid == 0) { shs[w] = s; shss[w] = ss; }
    __syncthreads();
    if (t == 0) {
        float ts = 0.f, tss = 0.f;
#pragma unroll
        for (int i = 0; i < 8; i++) { ts += shs[i]; tss += shss[i]; }
        invn[b] = rsqrtf(tss);
        rs[b] = ts;
    }
}

__global__ void rowstats_hl(const bf16* __restrict__ hi, const bf16* __restrict__ lo,
                            int D, float* __restrict__ invn, float* __restrict__ rs) {
    int b = blockIdx.x, t = threadIdx.x;   // 128 threads
    float s = 0.f, ss = 0.f;
    for (int i = t; i < D; i += 128) {
        float v = __bfloat162float(hi[(size_t)b * D + i]) +
                  __bfloat162float(lo[(size_t)b * D + i]);
        s += v;
        ss = fmaf(v, v, ss);
    }
    __shared__ float shs[4], shss[4];
    s = warp_sum(s); ss = warp_sum(ss);
    int w = t >> 5, lid = t & 31;
    if (lid == 0) { shs[w] = s; shss[w] = ss; }
    __syncthreads();
    if (t == 0) {
        float ts = 0.f, tss = 0.f;
#pragma unroll
        for (int i = 0; i < 4; i++) { ts += shs[i]; tss += shss[i]; }
        invn[b] = rsqrtf(tss);
        rs[b] = ts;
    }
}

// ================= hebbian-path kernels =================
__global__ void cb_kernel(const float* __restrict__ T, int Y,
                          const float* __restrict__ invnx, const float* __restrict__ sb,
                          float* __restrict__ cb) {
    int wrp = (blockIdx.x * blockDim.x + threadIdx.x) >> 5;
    int lane = threadIdx.x & 31;
    if (wrp >= 8192) return;
    const float* row = T + (size_t)wrp * Y;
    float ss = 0.f;
    for (int i = lane; i < Y; i += 32) { float v = row[i]; ss = fmaf(v, v, ss); }
    ss = warp_sum(ss);
    if (lane == 0) cb[wrp] = sb[wrp] * invnx[wrp] * rsqrtf(ss);
}

__global__ void hebb_kernel(const float* __restrict__ T, int Y,
                            const float* __restrict__ cb, float* __restrict__ part) {
    int j = threadIdx.x;
    int b0 = blockIdx.x * 32;
    float a0 = 0.f, a1 = 0.f, a2 = 0.f, a3 = 0.f;
#pragma unroll
    for (int b = b0; b < b0 + 32; b += 4) {
        a0 = fmaf(T[(size_t)b * Y + j],       cb[b],     a0);
        a1 = fmaf(T[(size_t)(b + 1) * Y + j], cb[b + 1], a1);
        a2 = fmaf(T[(size_t)(b + 2) * Y + j], cb[b + 2], a2);
        a3 = fmaf(T[(size_t)(b + 3) * Y + j], cb[b + 3], a3);
    }
    part[blockIdx.x * Y + j] = (a0 + a1) + (a2 + a3);
}

// one block per row
__global__ void rowsum_kernel(const float* __restrict__ H, int D,
                              float* __restrict__ out) {
    int row = blockIdx.x, t = threadIdx.x;   // 128 threads
    float s = 0.f;
    for (int i = t; i < D; i += 128) s += H[(size_t)row * D + i];
    __shared__ float sh[4];
    s = warp_sum(s);
    if ((t & 31) == 0) sh[t >> 5] = s;
    __syncthreads();
    if (t == 0) out[row] = sh[0] + sh[1] + sh[2] + sh[3];
}

__global__ void score_kernel(const float* __restrict__ rsH, const float* __restrict__ part,
                             int Y, float* __restrict__ hm) {
    int j = threadIdx.x;
    float hb = 0.f;
    for (int p = 0; p < 256; p++) hb += part[p * Y + j];
    float theta = 1.0f / (float)Y;
    float sc = fmaf(1.0f - theta, rsH[j], hb);
    __shared__ float smin[256], smax[256];
    smin[j] = sc; smax[j] = sc;
    __syncthreads();
    for (int s = blockDim.x >> 1; s > 0; s >>= 1) {
        if (j < s) {
            smin[j] = fminf(smin[j], smin[j + s]);
            smax[j] = fmaxf(smax[j], smax[j + s]);
        }
        __syncthreads();
    }
    float mn = smin[0], mx = smax[0];
    float norm = (sc - mn) / (mx - mn + 1e-8f);
    hm[j] = (norm < 0.5f) ? 0.0f : 1.0f;
}

// ================= launcher =================
extern "C" void kernel_launch(void* const* d_in, const int* in_sizes, int n_in,
                              void* d_out, int out_size) {
    const float* x     = (const float*)d_in[0];
    const float* mask0 = (const float*)d_in[1];
    const float* mask1 = (const float*)d_in[2];
    const float* mask2 = (const float*)d_in[3];
    const float* W1 = (const float*)d_in[4];
    const float* b1 = (const float*)d_in[5];
    const float* W2 = (const float*)d_in[6];
    const float* b2 = (const float*)d_in[7];
    const float* W3 = (const float*)d_in[8];
    const float* b3 = (const float*)d_in[9];
    const float* W4 = (const float*)d_in[10];
    const float* b4 = (const float*)d_in[11];
    const float* H1 = (const float*)d_in[12];
    const float* H2 = (const float*)d_in[13];
    const float* H3 = (const float*)d_in[14];
    float* out = (float*)d_out;

    bf16 *xh, *xl, *x1h, *x1l, *x2h, *x2l, *x3h, *x3l;
    bf16 *B1h, *B1l, *B2h, *B2l, *B3h, *B3l, *B4h, *B4l;
    float *t1, *t2, *t3, *invn, *sbp, *cbp, *part1, *part2, *part3, *rsH;
    cudaGetSymbolAddress((void**)&xh, g_xh);   cudaGetSymbolAddress((void**)&xl, g_xl);
    cudaGetSymbolAddress((void**)&x1h, g_x1h); cudaGetSymbolAddress((void**)&x1l, g_x1l);
    cudaGetSymbolAddress((void**)&x2h, g_x2h); cudaGetSymbolAddress((void**)&x2l, g_x2l);
    cudaGetSymbolAddress((void**)&x3h, g_x3h); cudaGetSymbolAddress((void**)&x3l, g_x3l);
    cudaGetSymbolAddress((void**)&B1h, g_B1h); cudaGetSymbolAddress((void**)&B1l, g_B1l);
    cudaGetSymbolAddress((void**)&B2h, g_B2h); cudaGetSymbolAddress((void**)&B2l, g_B2l);
    cudaGetSymbolAddress((void**)&B3h, g_B3h); cudaGetSymbolAddress((void**)&B3l, g_B3l);
    cudaGetSymbolAddress((void**)&B4h, g_B4h); cudaGetSymbolAddress((void**)&B4l, g_B4l);
    cudaGetSymbolAddress((void**)&t1, g_t1);
    cudaGetSymbolAddress((void**)&t2, g_t2);
    cudaGetSymbolAddress((void**)&t3, g_t3);
    cudaGetSymbolAddress((void**)&invn, g_invn);
    cudaGetSymbolAddress((void**)&sbp, g_sb);
    cudaGetSymbolAddress((void**)&cbp, g_cb);
    cudaGetSymbolAddress((void**)&part1, g_part1);
    cudaGetSymbolAddress((void**)&part2, g_part2);
    cudaGetSymbolAddress((void**)&part3, g_part3);
    cudaGetSymbolAddress((void**)&rsH, g_rsH);

    float* invn1 = invn;        float* invn2 = invn + 8192;  float* invn3 = invn + 16384;
    float* sb1 = sbp;           float* sb2 = sbp + 8192;     float* sb3 = sbp + 16384;
    float* cb1 = cbp;           float* cb2 = cbp + 8192;     float* cb3 = cbp + 16384;

    static bool inited = false;
    static cudaStream_t s1, s2, s3;
    static cudaEvent_t eFork, eW, eR, eG1, eG2, eG3, eS1, eS2, eS3;
    if (!inited) {
        cudaFuncSetAttribute(gemm_mma, cudaFuncAttributeMaxDynamicSharedMemorySize,
                             GEMM_SMEM);
        cudaStreamCreateWithFlags(&s1, cudaStreamNonBlocking);
        cudaStreamCreateWithFlags(&s2, cudaStreamNonBlocking);
        cudaStreamCreateWithFlags(&s3, cudaStreamNonBlocking);
        cudaEventCreateWithFlags(&eFork, cudaEventDisableTiming);
        cudaEventCreateWithFlags(&eW, cudaEventDisableTiming);
        cudaEventCreateWithFlags(&eR, cudaEventDisableTiming);
        cudaEventCreateWithFlags(&eG1, cudaEventDisableTiming);
        cudaEventCreateWithFlags(&eG2, cudaEventDisableTiming);
        cudaEventCreateWithFlags(&eG3, cudaEventDisableTiming);
        cudaEventCreateWithFlags(&eS1, cudaEventDisableTiming);
        cudaEventCreateWithFlags(&eS2, cudaEventDisableTiming);
        cudaEventCreateWithFlags(&eS3, cudaEventDisableTiming);
        inited = true;
    }

    const int B = 8192;
    const size_t OUT_OFF = (size_t)B * 1000;

    // ---- fork side streams off the capture stream ----
    cudaEventRecord(eFork, 0);
    cudaStreamWaitEvent(s1, eFork, 0);
    cudaStreamWaitEvent(s2, eFork, 0);
    cudaStreamWaitEvent(s3, eFork, 0);

    // s1: weight conversion (gemm1 gate)
    split_weights<<<dim3(256, 7), 256, 0, s1>>>(W1, H1, W2, H2, W3, H3, W4,
                                                B1h, B1l, B2h, B2l, B3h, B3l,
                                                B4h, B4l);
    cudaEventRecord(eW, s1);

    // s2: H rowsums (score gates)
    rowsum_kernel<<<256, 128, 0, s2>>>(H1, 1024, rsH);
    rowsum_kernel<<<128, 128, 0, s2>>>(H2, 256, rsH + 256);
    rowsum_kernel<<<64, 128, 0, s2>>>(H3, 128, rsH + 384);
    cudaEventRecord(eR, s2);

    // s0: x conversion + stats
    rowstats_split<<<B, 256>>>(x, invn1, sb1, xh, xl);

    // ---- layer 1 GEMM on s0 ----
    cudaStreamWaitEvent(0, eW, 0);
    gemm_mma<<<dim3(4, 64), 256, GEMM_SMEM>>>(xh, xl, B1h, B1l, b1, mask0,
                                              x1h, x1l, nullptr, t1, 1024, 256, 256);
    cudaEventRecord(eG1, 0);

    // layer-1 hebb chain on s1 (overlaps gemm2..4)
    cudaStreamWaitEvent(s1, eG1, 0);
    cudaStreamWaitEvent(s1, eR, 0);
    cb_kernel<<<1024, 256, 0, s1>>>(t1, 256, invn1, sb1, cb1);
    hebb_kernel<<<256, 256, 0, s1>>>(t1, 256, cb1, part1);
    score_kernel<<<1, 256, 0, s1>>>(rsH, part1, 256, out + OUT_OFF);
    cudaEventRecord(eS1, s1);

    // ---- layer 2 on s0 ----
    rowstats_hl<<<B, 128>>>(x1h, x1l, 256, invn2, sb2);
    gemm_mma<<<dim3(2, 64), 256, GEMM_SMEM>>>(x1h, x1l, B2h, B2l, b2, mask1,
                                              x2h, x2l, nullptr, t2, 256, 128, 128);
    cudaEventRecord(eG2, 0);

    // layer-2 hebb chain on s2
    cudaStreamWaitEvent(s2, eG2, 0);
    cb_kernel<<<1024, 256, 0, s2>>>(t2, 128, invn2, sb2, cb2);
    hebb_kernel<<<256, 128, 0, s2>>>(t2, 128, cb2, part2);
    score_kernel<<<1, 128, 0, s2>>>(rsH + 256, part2, 128, out + OUT_OFF + 256);
    cudaEventRecord(eS2, s2);

    // ---- layer 3 on s0 ----
    rowstats_hl<<<B, 128>>>(x2h, x2l, 128, invn3, sb3);
    gemm_mma<<<dim3(1, 64), 256, GEMM_SMEM>>>(x2h, x2l, B3h, B3l, b3, mask2,
                                              x3h, x3l, nullptr, t3, 128, 64, 64);
    cudaEventRecord(eG3, 0);

    // layer-3 hebb chain on s3
    cudaStreamWaitEvent(s3, eG3, 0);
    cudaStreamWaitEvent(s3, eR, 0);
    cb_kernel<<<1024, 256, 0, s3>>>(t3, 64, invn3, sb3, cb3);
    hebb_kernel<<<256, 64, 0, s3>>>(t3, 64, cb3, part3);
    score_kernel<<<1, 64, 0, s3>>>(rsH + 384, part3, 64, out + OUT_OFF + 384);
    cudaEventRecord(eS3, s3);

    // ---- layer 4 on s0 ----
    gemm_mma<<<dim3(8, 64), 256, GEMM_SMEM>>>(x3h, x3l, B4h, B4l, b4,
                                              (const float*)nullptr,
                                              (bf16*)nullptr, (bf16*)nullptr,
                                              out, (float*)nullptr, 64, 1000, 0);

    // ---- join ----
    cudaStreamWaitEvent(0, eS1, 0);
    cudaStreamWaitEvent(0, eS2, 0);
    cudaStreamWaitEvent(0, eS3, 0);
}